// round 5
// baseline (speedup 1.0000x reference)
#include <cuda_runtime.h>
#include <cstdint>

#define NROWS 8192
#define DDIM  256
#define BM    64
#define BN    64
#define NITER (NROWS/BN)
#define EPSF  1e-6f

#define NTHREADS 512

#define QS_STRIDE 260
#define PS_STRIDE 68

#define QS_FLOATS (BM*QS_STRIDE)   // 16640
#define KS_FLOATS (BN*DDIM)        // 16384 per buffer (swizzled, no pad)
#define PS_FLOATS (BM*PS_STRIDE)   // 4352
#define SMEM_FLOATS (QS_FLOATS + 2*KS_FLOATS + PS_FLOATS + 4*BM)
#define SMEM_BYTES  (SMEM_FLOATS*4)

__device__ float  g_qtf[(size_t)NROWS*DDIM];  // tf32-rounded copy of q (8MB)
__device__ float2 g_qt[NROWS];                // (||q||^2, 1/t)

__device__ __forceinline__ float f2tf32f(float x) {
    unsigned r;
    asm("cvt.rna.tf32.f32 %0, %1;" : "=r"(r) : "f"(x));
    return __uint_as_float(r);
}

__device__ __forceinline__ float flg2(float x) {
    float r;
    asm("lg2.approx.f32 %0, %1;" : "=f"(r) : "f"(x));
    return r;
}

__device__ __forceinline__ float fex2(float x) {
    float r;
    asm("ex2.approx.f32 %0, %1;" : "=f"(r) : "f"(x));
    return r;
}

__device__ __forceinline__ void mma_tf32(float d[4],
    unsigned a0, unsigned a1, unsigned a2, unsigned a3,
    unsigned b0, unsigned b1) {
    asm volatile(
        "mma.sync.aligned.m16n8k8.row.col.f32.tf32.tf32.f32 "
        "{%0,%1,%2,%3}, {%4,%5,%6,%7}, {%8,%9}, {%0,%1,%2,%3};\n"
        : "+f"(d[0]), "+f"(d[1]), "+f"(d[2]), "+f"(d[3])
        : "r"(a0), "r"(a1), "r"(a2), "r"(a3), "r"(b0), "r"(b1));
}

// ---------------- prep: tf32 copy + row stats ----------------
__global__ void prep_kernel(const float* __restrict__ q, const float* __restrict__ cp) {
    int row  = blockIdx.x * 8 + (threadIdx.x >> 5);
    int lane = threadIdx.x & 31;
    const float4* qr = (const float4*)(q + (size_t)row * DDIM);
    float4* wr       = (float4*)(g_qtf + (size_t)row * DDIM);
    float s = 0.0f;
#pragma unroll
    for (int i = 0; i < 2; i++) {
        float4 v = qr[lane + i * 32];
        s += v.x * v.x + v.y * v.y + v.z * v.z + v.w * v.w;
        wr[lane + i * 32] = make_float4(f2tf32f(v.x), f2tf32f(v.y),
                                        f2tf32f(v.z), f2tf32f(v.w));
    }
#pragma unroll
    for (int o = 16; o > 0; o >>= 1) s += __shfl_xor_sync(0xffffffffu, s, o);
    if (lane == 0) {
        float cc = fmaxf(*cp, EPSF);
        g_qt[row] = make_float2(s, 1.0f / fmaxf(1.0f - cc * s, EPSF));
    }
}

// p = exp(-acosh(arg)/sqrt(c)) = 2^(-k*log2(y)),  y = arg + sqrt((arg-1)(arg+1))
__device__ __forceinline__ float pcalc(float s, float qni, float coef, float qnj, float kf) {
    float diff = fmaxf(qni + qnj - 2.0f * s, 0.0f);
    float arg  = fmaf(coef, diff, 1.0f);
    arg = fmaxf(arg, 1.0f + EPSF) + EPSF;
    float x = arg - 1.0f;
    float y = arg + sqrtf(x * (arg + 1.0f));
    return fex2(-kf * flg2(y));
}

__global__ __launch_bounds__(NTHREADS, 1)
void hyp_attn_kernel(const float* __restrict__ cp, float* __restrict__ out) {
    extern __shared__ float smem[];
    float* Qs   = smem;                        // [BM][QS_STRIDE]
    float* Ks   = Qs + QS_FLOATS;              // 2 x [BN][256] swizzled
    float* Ps   = Ks + 2 * KS_FLOATS;          // [BM][PS_STRIDE]
    float* lred = Ps + PS_FLOATS;              // [4][BM]

    uint32_t smem_u32;
    asm("{ .reg .u64 t; cvta.to.shared.u64 t, %1; cvt.u32.u64 %0, t; }"
        : "=r"(smem_u32) : "l"(smem));
    const uint32_t ks_u32 = smem_u32 + QS_FLOATS * 4;

    const int tid  = threadIdx.x;
    const int w    = tid >> 5;      // 0..15
    const int lane = tid & 31;
    const int g    = lane >> 2;
    const int tg   = lane & 3;

    const float cc         = fmaxf(*cp, EPSF);
    const float two_c      = 2.0f * cc;
    const float kf         = 1.0f / sqrtf(cc);

    const int rowbase = blockIdx.x * BM;

    // GEMM1 warp coords: 4(m) x 4(n), warp tile 16x16 of S
    const int wm = w >> 2;
    const int wn = w & 3;
    const int lr0 = wm * 16 + g;
    const int lr1 = lr0 + 8;
    const float2 qt0 = g_qt[rowbase + lr0];
    const float2 qt1 = g_qt[rowbase + lr1];
    const float qni0 = qt0.x, qni1 = qt1.x;
    const float tc0  = two_c * qt0.y;
    const float tc1  = two_c * qt1.y;
    const int grow0 = rowbase + lr0;
    const int grow1 = rowbase + lr1;

    // GEMM2 warp coords: 4(m) x 4(n), warp tile 16x64 of O
    const int wm2 = w & 3;
    const int wn2 = w >> 2;
    const int r2  = wm2 * 16 + g;   // O local rows r2, r2+8

    // swizzle constants (GEMM1 B access)
    const int g3h = (g & 3) << 3;
    const int g4  = g & 4;
    const int tA  = tg + g4;
    const int tB  = tg + (4 ^ g4);

    // ---- prologue: Q tile (already tf32) ----
    {
        const float4* src = (const float4*)(g_qtf + ((size_t)rowbase << 8));
#pragma unroll
        for (int i = 0; i < 8; i++) {
            int f  = tid + i * NTHREADS;
            int r  = f >> 6;
            int c4 = f & 63;
            *(float4*)(Qs + r * QS_STRIDE + c4 * 4) = src[(r << 6) + c4];
        }
    }

    // ---- prologue: issue cp.async for K(0) into buf0 ----
    {
        const float* src0 = g_qtf;
#pragma unroll
        for (int i = 0; i < 8; i++) {
            int f  = tid + i * NTHREADS;
            int r  = f >> 6;
            int c4 = f & 63;
            int csw = c4 ^ (((r & 3) << 1) | ((r >> 2) & 1));
            uint32_t dst = ks_u32 + (r << 10) + (csw << 4);
            asm volatile("cp.async.cg.shared.global [%0], [%1], 16;\n"
                         :: "r"(dst), "l"(src0 + (r << 8) + (c4 << 2)) : "memory");
        }
        asm volatile("cp.async.commit_group;\n" ::: "memory");
    }

    float of[8][4];
#pragma unroll
    for (int nt = 0; nt < 8; nt++)
#pragma unroll
        for (int e = 0; e < 4; e++) of[nt][e] = 0.0f;

    float rsum0 = 0.0f, rsum1 = 0.0f;

    for (int jt = 0; jt < NITER; jt++) {
        const int jbase = jt * BN;
        const float* Kb = Ks + (jt & 1) * KS_FLOATS;

        asm volatile("cp.async.wait_group 0;\n" ::: "memory");
        __syncthreads();   // B1: K(jt) visible; Ps free; GEMM2(jt-1) done

        // prefetch K(jt+1) into the other buffer (overlaps with this iter)
        if (jt + 1 < NITER) {
            const float* srcN = g_qtf + ((size_t)(jbase + BN) << 8);
            uint32_t base = ks_u32 + ((jt + 1) & 1) * (KS_FLOATS * 4);
#pragma unroll
            for (int i = 0; i < 8; i++) {
                int f  = tid + i * NTHREADS;
                int r  = f >> 6;
                int c4 = f & 63;
                int csw = c4 ^ (((r & 3) << 1) | ((r >> 2) & 1));
                uint32_t dst = base + (r << 10) + (csw << 4);
                asm volatile("cp.async.cg.shared.global [%0], [%1], 16;\n"
                             :: "r"(dst), "l"(srcN + (r << 8) + (c4 << 2)) : "memory");
            }
            asm volatile("cp.async.commit_group;\n" ::: "memory");
        }

        // ---- GEMM1: S = Q . K^T  (warp tile 16x16) ----
        float sf[2][4];
#pragma unroll
        for (int nt = 0; nt < 2; nt++)
#pragma unroll
            for (int e = 0; e < 4; e++) sf[nt][e] = 0.0f;

        const float* A0 = Qs + lr0 * QS_STRIDE;
        const float* A1 = Qs + lr1 * QS_STRIDE;
        const float* Bp0 = Kb + ((wn * 16 + 0 + g) << 8);
        const float* Bp1 = Kb + ((wn * 16 + 8 + g) << 8);
#pragma unroll 8
        for (int kk = 0; kk < DDIM; kk += 8) {
            const int kx = kk ^ g3h;
            unsigned a0 = __float_as_uint(A0[kk + tg]);
            unsigned a1 = __float_as_uint(A1[kk + tg]);
            unsigned a2 = __float_as_uint(A0[kk + tg + 4]);
            unsigned a3 = __float_as_uint(A1[kk + tg + 4]);
            mma_tf32(sf[0], a0, a1, a2, a3,
                     __float_as_uint(Bp0[kx + tA]), __float_as_uint(Bp0[kx + tB]));
            mma_tf32(sf[1], a0, a1, a2, a3,
                     __float_as_uint(Bp1[kx + tA]), __float_as_uint(Bp1[kx + tB]));
        }

        // ---- transform: p = exp(-dist), accumulate l, store P (tf32) ----
#pragma unroll
        for (int nt = 0; nt < 2; nt++) {
            const int cbase = wn * 16 + nt * 8 + tg * 2;
            const int col0  = jbase + cbase;
            float4 qq = *(const float4*)((const float*)&g_qt[col0]);
            float p00 = pcalc(sf[nt][0], qni0, tc0 * qq.y, qq.x, kf);
            float p01 = pcalc(sf[nt][1], qni0, tc0 * qq.w, qq.z, kf);
            float p10 = pcalc(sf[nt][2], qni1, tc1 * qq.y, qq.x, kf);
            float p11 = pcalc(sf[nt][3], qni1, tc1 * qq.w, qq.z, kf);
            if (col0     == grow0) p00 = 1.0f;
            if (col0 + 1 == grow0) p01 = 1.0f;
            if (col0     == grow1) p10 = 1.0f;
            if (col0 + 1 == grow1) p11 = 1.0f;
            rsum0 += p00 + p01;
            rsum1 += p10 + p11;
            *(float2*)(Ps + lr0 * PS_STRIDE + cbase) =
                make_float2(f2tf32f(p00), f2tf32f(p01));
            *(float2*)(Ps + lr1 * PS_STRIDE + cbase) =
                make_float2(f2tf32f(p10), f2tf32f(p11));
        }
        __syncthreads();   // B2: P visible

        // ---- GEMM2: O += P . V  (warp tile 16x64) ----
#pragma unroll
        for (int kk = 0; kk < BN; kk += 8) {
            const float* Pr0 = Ps + (wm2 * 16 + g) * PS_STRIDE + kk;
            const float* Pr1 = Pr0 + 8 * PS_STRIDE;
            unsigned a0 = __float_as_uint(Pr0[tg]);
            unsigned a1 = __float_as_uint(Pr1[tg]);
            unsigned a2 = __float_as_uint(Pr0[tg + 4]);
            unsigned a3 = __float_as_uint(Pr1[tg + 4]);
            const float* V0 = Kb + ((kk + tg) << 8);
            const float* V1 = Kb + ((kk + tg + 4) << 8);
#pragma unroll
            for (int nt = 0; nt < 8; nt++) {
                const int cnt = ((wn2 << 6) + (nt << 3) + g) ^ (tg << 3);
                unsigned b0 = __float_as_uint(V0[cnt]);
                unsigned b1 = __float_as_uint(V1[cnt ^ 4]);
                mma_tf32(of[nt], a0, a1, a2, a3, b0, b1);
            }
        }
        // no end barrier needed: next iteration's B1 orders buffer reuse
    }

    // ---- reduce row sums (4 warp partials per row) ----
    rsum0 += __shfl_xor_sync(0xffffffffu, rsum0, 1);
    rsum0 += __shfl_xor_sync(0xffffffffu, rsum0, 2);
    rsum1 += __shfl_xor_sync(0xffffffffu, rsum1, 1);
    rsum1 += __shfl_xor_sync(0xffffffffu, rsum1, 2);
    if (tg == 0) { lred[wn * BM + lr0] = rsum0; lred[wn * BM + lr1] = rsum1; }
    __syncthreads();

    // ---- epilogue: O / l ----
    {
        const float li0 = 1.0f / (lred[r2] + lred[BM + r2] +
                                  lred[2 * BM + r2] + lred[3 * BM + r2]);
        const float li1 = 1.0f / (lred[r2 + 8] + lred[BM + r2 + 8] +
                                  lred[2 * BM + r2 + 8] + lred[3 * BM + r2 + 8]);
        const int grA = rowbase + r2;
#pragma unroll
        for (int nt = 0; nt < 8; nt++) {
            const int col = wn2 * 64 + nt * 8 + tg * 2;
            *(float2*)(out + (size_t)grA * DDIM + col) =
                make_float2(of[nt][0] * li0, of[nt][1] * li0);
            *(float2*)(out + (size_t)(grA + 8) * DDIM + col) =
                make_float2(of[nt][2] * li1, of[nt][3] * li1);
        }
    }
}

extern "C" void kernel_launch(void* const* d_in, const int* in_sizes, int n_in,
                              void* d_out, int out_size) {
    const float* q  = (const float*)d_in[0];
    const float* cp = (const float*)d_in[1];
    float* out      = (float*)d_out;

    cudaFuncSetAttribute(hyp_attn_kernel,
                         cudaFuncAttributeMaxDynamicSharedMemorySize, SMEM_BYTES);

    prep_kernel<<<NROWS / 8, 256>>>(q, cp);
    hyp_attn_kernel<<<NROWS / BM, NTHREADS, SMEM_BYTES>>>(cp, out);
}

// round 7
// speedup vs baseline: 1.0200x; 1.0200x over previous
#include <cuda_runtime.h>
#include <cstdint>

#define NROWS 8192
#define DDIM  256
#define BM    64
#define BN    64
#define NITER (NROWS/BN)
#define EPSF  1e-6f

#define NTHREADS 512

#define Q2_STRIDE 260      // f2 stride, 260*2 % 32 == 8 -> conflict-free LDS.64
#define P2_STRIDE 68       // f2 stride, 68*2 % 32 == 8 (reads conflict-free)

#define Q2_F2 (32*Q2_STRIDE)          // 8320 f2
#define KS_FLOATS (BN*DDIM)           // 16384 floats per buffer
#define P2_F2 (32*P2_STRIDE)          // 2176 f2
#define SMEM_FLOATS (2*Q2_F2 + 2*KS_FLOATS + 2*P2_F2 + 4*BM)
#define SMEM_BYTES  (SMEM_FLOATS*4)   // ~216 KB

// d-paired, tf32-rounded copy of q: f2 slot s of row r = (q[r][k_s], q[r][k_s+4]),
// k_s = (s>>2)*8 + (s&3)
__device__ float  g_qtf[(size_t)NROWS*DDIM];
__device__ float2 g_qt[NROWS];        // (||q||^2, 1/t)

__device__ __forceinline__ float f2tf32f(float x) {
    unsigned r;
    asm("cvt.rna.tf32.f32 %0, %1;" : "=r"(r) : "f"(x));
    return __uint_as_float(r);
}
__device__ __forceinline__ float flg2(float x) {
    float r; asm("lg2.approx.f32 %0, %1;" : "=f"(r) : "f"(x)); return r;
}
__device__ __forceinline__ float fex2(float x) {
    float r; asm("ex2.approx.f32 %0, %1;" : "=f"(r) : "f"(x)); return r;
}

__device__ __forceinline__ void mma_tf32(float d[4],
    unsigned a0, unsigned a1, unsigned a2, unsigned a3,
    unsigned b0, unsigned b1) {
    asm volatile(
        "mma.sync.aligned.m16n8k8.row.col.f32.tf32.tf32.f32 "
        "{%0,%1,%2,%3}, {%4,%5,%6,%7}, {%8,%9}, {%0,%1,%2,%3};\n"
        : "+f"(d[0]), "+f"(d[1]), "+f"(d[2]), "+f"(d[3])
        : "r"(a0), "r"(a1), "r"(a2), "r"(a3), "r"(b0), "r"(b1));
}

// ---------------- prep: tf32 + d-paired copy + row stats ----------------
__global__ void prep_kernel(const float* __restrict__ q, const float* __restrict__ cp) {
    int row  = blockIdx.x * 8 + (threadIdx.x >> 5);
    int lane = threadIdx.x & 31;      // = k-group (8 d's each)
    const float4* qr = (const float4*)(q + (size_t)row * DDIM);
    float4 A = qr[lane * 2];          // d = 8*lane .. +3
    float4 B = qr[lane * 2 + 1];      // d = 8*lane+4 .. +7
    float s = A.x*A.x + A.y*A.y + A.z*A.z + A.w*A.w
            + B.x*B.x + B.y*B.y + B.z*B.z + B.w*B.w;
    A = make_float4(f2tf32f(A.x), f2tf32f(A.y), f2tf32f(A.z), f2tf32f(A.w));
    B = make_float4(f2tf32f(B.x), f2tf32f(B.y), f2tf32f(B.z), f2tf32f(B.w));
    float4* wr = (float4*)(g_qtf + (size_t)row * DDIM + lane * 8);
    wr[0] = make_float4(A.x, B.x, A.y, B.y);   // f2 slots 4l, 4l+1
    wr[1] = make_float4(A.z, B.z, A.w, B.w);   // f2 slots 4l+2, 4l+3
#pragma unroll
    for (int o = 16; o > 0; o >>= 1) s += __shfl_xor_sync(0xffffffffu, s, o);
    if (lane == 0) {
        float cc = fmaxf(*cp, EPSF);
        g_qt[row] = make_float2(s, 1.0f / fmaxf(1.0f - cc * s, EPSF));
    }
}

__device__ __forceinline__ float pcalc(float s, float qni, float coef, float qnj, float kf) {
    float diff = fmaxf(qni + qnj - 2.0f * s, 0.0f);
    float arg  = fmaf(coef, diff, 1.0f);
    arg = fmaxf(arg, 1.0f + EPSF) + EPSF;
    float x = arg - 1.0f;
    float y = arg + sqrtf(x * (arg + 1.0f));
    return fex2(-kf * flg2(y));
}

__global__ __launch_bounds__(NTHREADS, 1)
void hyp_attn_kernel(const float* __restrict__ cp, float* __restrict__ out) {
    extern __shared__ float smem[];
    float2* Q2  = (float2*)smem;                        // [32][Q2_STRIDE] row-paired
    float*  Ks  = smem + 2 * Q2_F2;                     // 2 x [64][256] d-paired+swz
    float2* P2  = (float2*)(Ks + 2 * KS_FLOATS);        // [32][P2_STRIDE] row-paired
    float*  lred = (float*)(P2 + P2_F2);                // [4][BM]

    uint32_t smem_u32;
    asm("{ .reg .u64 t; cvta.to.shared.u64 t, %1; cvt.u32.u64 %0, t; }"
        : "=r"(smem_u32) : "l"(smem));
    const uint32_t ks_u32 = smem_u32 + 2 * Q2_F2 * 4;

    const int tid  = threadIdx.x;
    const int w    = tid >> 5;      // 0..15
    const int lane = tid & 31;
    const int g    = lane >> 2;
    const int tg   = lane & 3;
    const int g3   = g & 3;
    const int ghi  = g >> 2;        // 0/1

    const float cc    = fmaxf(*cp, EPSF);
    const float two_c = 2.0f * cc;
    const float kf    = 1.0f / sqrtf(cc);

    const int rowbase = blockIdx.x * BM;

    // GEMM1: 4(m-quad) x 4(n) warps; warp tile 16x16 of S
    const int wm = w >> 2;          // quad id; also GEMM2 m-strip
    const int wn = w & 3;
    const int lr0 = wm * 16 + g;
    const int lr1 = lr0 + 8;
    const float2 qt0 = g_qt[rowbase + lr0];
    const float2 qt1 = g_qt[rowbase + lr1];
    const float qni0 = qt0.x, qni1 = qt1.x;
    const float tc0  = two_c * qt0.y;
    const float tc1  = two_c * qt1.y;
    const int grow0 = rowbase + lr0;
    const int grow1 = rowbase + lr1;

    // GEMM2: same m-strip (wm), n-chunk wn*64
    const int w8 = wn * 8;             // (col>>3) base for GEMM2 B
    const int g21c = (g3 << 1) | ghi;  // float-offset decoding col within 8-block

    // ---- prologue: build row-paired Q'' from d-paired g_qtf ----
    {
        // 32 pair-rows x 64 float4-groups = 2048 tasks
#pragma unroll
        for (int i = 0; i < 4; i++) {
            int t  = tid + i * NTHREADS;
            int rp = t >> 6;            // pair row 0..31
            int m  = t & 63;            // float4 group
            int rA = ((rp >> 3) << 4) + (rp & 7);
            int rB = rA + 8;
            const float4* pA = (const float4*)(g_qtf + (((size_t)(rowbase + rA)) << 8));
            const float4* pB = (const float4*)(g_qtf + (((size_t)(rowbase + rB)) << 8));
            float4 X = pA[m];
            float4 Y = pB[m];
            // source slots 2m,2m+1 hold (qA[k0],qA[k0+4]),(qA[k0+1],qA[k0+1+4])
            int k0 = ((m >> 1) << 3) + ((2 * m) & 3);
            float4* dst0 = (float4*)(Q2 + rp * Q2_STRIDE + k0);
            float4* dst1 = (float4*)(Q2 + rp * Q2_STRIDE + k0 + 4);
            *dst0 = make_float4(X.x, Y.x, X.z, Y.z);   // f2 k0, k0+1
            *dst1 = make_float4(X.y, Y.y, X.w, Y.w);   // f2 k0+4, k0+5
        }
    }

    // ---- prologue: cp.async K(0) into buf0 (swizzle chunks by row) ----
    {
        const float* src0 = g_qtf;
#pragma unroll
        for (int i = 0; i < 8; i++) {
            int f  = tid + i * NTHREADS;
            int r  = f >> 6;
            int c  = f & 63;
            int cs = c ^ (2 * (r & 3));
            uint32_t dst = ks_u32 + (r << 10) + (cs << 4);
            asm volatile("cp.async.cg.shared.global [%0], [%1], 16;\n"
                         :: "r"(dst), "l"(src0 + (r << 8) + (c << 2)) : "memory");
        }
        asm volatile("cp.async.commit_group;\n" ::: "memory");
    }

    float of[8][4];
#pragma unroll
    for (int nt = 0; nt < 8; nt++)
#pragma unroll
        for (int e = 0; e < 4; e++) of[nt][e] = 0.0f;

    float rsum0 = 0.0f, rsum1 = 0.0f;

    const float2* Arow = Q2 + (wm * 8 + g) * Q2_STRIDE;
    const float2* Prow = P2 + (wm * 8 + g) * P2_STRIDE;
    float2* Pwr = P2 + (wm * 8 + g) * P2_STRIDE;

    for (int jt = 0; jt < NITER; jt++) {
        const int jbase = jt * BN;
        const float* Kb = Ks + (jt & 1) * KS_FLOATS;

        asm volatile("cp.async.wait_group 0;\n" ::: "memory");
        __syncthreads();   // B1: K(jt) ready; all GEMM2(jt-1) done

        if (jt + 1 < NITER) {
            const float* srcN = g_qtf + ((size_t)(jbase + BN) << 8);
            uint32_t base = ks_u32 + ((jt + 1) & 1) * (KS_FLOATS * 4);
#pragma unroll
            for (int i = 0; i < 8; i++) {
                int f  = tid + i * NTHREADS;
                int r  = f >> 6;
                int c  = f & 63;
                int cs = c ^ (2 * (r & 3));
                uint32_t dst = base + (r << 10) + (cs << 4);
                asm volatile("cp.async.cg.shared.global [%0], [%1], 16;\n"
                             :: "r"(dst), "l"(srcN + (r << 8) + (c << 2)) : "memory");
            }
            asm volatile("cp.async.commit_group;\n" ::: "memory");
        }

        // ---- GEMM1: S = Q.K^T (warp tile 16x16) ----
        float sf[2][4];
#pragma unroll
        for (int nt = 0; nt < 2; nt++)
#pragma unroll
            for (int e = 0; e < 4; e++) sf[nt][e] = 0.0f;

        const float2* Bp0 = (const float2*)(Kb + ((wn * 16 + 0 + g) << 8));
        const float2* Bp1 = (const float2*)(Kb + ((wn * 16 + 8 + g) << 8));
#pragma unroll 8
        for (int kg = 0; kg < 32; kg++) {
            float2 a01 = Arow[kg * 8 + tg];
            float2 a23 = Arow[kg * 8 + tg + 4];
            int slot = ((kg ^ g3) << 2) + tg;
            float2 b0 = Bp0[slot];
            float2 b1 = Bp1[slot];
            mma_tf32(sf[0], __float_as_uint(a01.x), __float_as_uint(a01.y),
                            __float_as_uint(a23.x), __float_as_uint(a23.y),
                            __float_as_uint(b0.x),  __float_as_uint(b0.y));
            mma_tf32(sf[1], __float_as_uint(a01.x), __float_as_uint(a01.y),
                            __float_as_uint(a23.x), __float_as_uint(a23.y),
                            __float_as_uint(b1.x),  __float_as_uint(b1.y));
        }

        // ---- transform: p = exp(-dist), accumulate l, store P (row-paired) ----
#pragma unroll
        for (int nt = 0; nt < 2; nt++) {
            const int cbase = wn * 16 + nt * 8 + tg * 2;
            const int col0  = jbase + cbase;
            float4 qq = *(const float4*)((const float*)&g_qt[col0]);
            float p00 = pcalc(sf[nt][0], qni0, tc0 * qq.y, qq.x, kf);
            float p01 = pcalc(sf[nt][1], qni0, tc0 * qq.w, qq.z, kf);
            float p10 = pcalc(sf[nt][2], qni1, tc1 * qq.y, qq.x, kf);
            float p11 = pcalc(sf[nt][3], qni1, tc1 * qq.w, qq.z, kf);
            if (col0     == grow0) p00 = 1.0f;
            if (col0 + 1 == grow0) p01 = 1.0f;
            if (col0     == grow1) p10 = 1.0f;
            if (col0 + 1 == grow1) p11 = 1.0f;
            rsum0 += p00 + p01;
            rsum1 += p10 + p11;
            *(float4*)(Pwr + cbase) = make_float4(
                f2tf32f(p00), f2tf32f(p10), f2tf32f(p01), f2tf32f(p11));
        }
        // quad-local barrier: only the 4 warps sharing this 16-row strip
        asm volatile("bar.sync %0, 128;\n" :: "r"(1 + wm) : "memory");

        // ---- GEMM2: O += P.V (warp tile 16x64) ----
#pragma unroll
        for (int kk = 0; kk < BN; kk += 8) {
            float2 a01 = Prow[kk + tg];
            float2 a23 = Prow[kk + tg + 4];
            unsigned a0 = __float_as_uint(a01.x), a1 = __float_as_uint(a01.y);
            unsigned a2 = __float_as_uint(a23.x), a3 = __float_as_uint(a23.y);
            const float* r0 = Kb + ((kk + tg) << 8);
            const float* r1 = Kb + ((kk + tg + 4) << 8);
#pragma unroll
            for (int nt = 0; nt < 8; nt++) {
                int off = ((w8 + nt) ^ tg) << 3;
                // both rows share the same chunk swizzle ((r&3)==tg), so the
                // in-row index is IDENTICAL for b0 and b1 (same output column)
                unsigned b0 = __float_as_uint(r0[off + g21c]);
                unsigned b1 = __float_as_uint(r1[off + g21c]);
                mma_tf32(of[nt], a0, a1, a2, a3, b0, b1);
            }
        }
        // no trailing barrier: next B1 (global) orders everything
    }

    // ---- reduce row sums (4 warp partials per row) ----
    rsum0 += __shfl_xor_sync(0xffffffffu, rsum0, 1);
    rsum0 += __shfl_xor_sync(0xffffffffu, rsum0, 2);
    rsum1 += __shfl_xor_sync(0xffffffffu, rsum1, 1);
    rsum1 += __shfl_xor_sync(0xffffffffu, rsum1, 2);
    if (tg == 0) { lred[wn * BM + lr0] = rsum0; lred[wn * BM + lr1] = rsum1; }
    __syncthreads();

    // ---- epilogue: O / l ----
    {
        const int r2 = wm * 16 + g;
        const float li0 = 1.0f / (lred[r2] + lred[BM + r2] +
                                  lred[2 * BM + r2] + lred[3 * BM + r2]);
        const float li1 = 1.0f / (lred[r2 + 8] + lred[BM + r2 + 8] +
                                  lred[2 * BM + r2 + 8] + lred[3 * BM + r2 + 8]);
        const int grA = rowbase + r2;
#pragma unroll
        for (int nt = 0; nt < 8; nt++) {
            const int col = wn * 64 + nt * 8 + tg * 2;
            *(float2*)(out + (size_t)grA * DDIM + col) =
                make_float2(of[nt][0] * li0, of[nt][1] * li0);
            *(float2*)(out + (size_t)(grA + 8) * DDIM + col) =
                make_float2(of[nt][2] * li1, of[nt][3] * li1);
        }
    }
}

extern "C" void kernel_launch(void* const* d_in, const int* in_sizes, int n_in,
                              void* d_out, int out_size) {
    const float* q  = (const float*)d_in[0];
    const float* cp = (const float*)d_in[1];
    float* out      = (float*)d_out;

    cudaFuncSetAttribute(hyp_attn_kernel,
                         cudaFuncAttributeMaxDynamicSharedMemorySize, SMEM_BYTES);

    prep_kernel<<<NROWS / 8, 256>>>(q, cp);
    hyp_attn_kernel<<<NROWS / BM, NTHREADS, SMEM_BYTES>>>(cp, out);
}

// round 8
// speedup vs baseline: 1.0205x; 1.0005x over previous
#include <cuda_runtime.h>
#include <cstdint>

#define NROWS 8192
#define DDIM  256
#define BM    64
#define BN    64
#define NITER (NROWS/BN)
#define EPSF  1e-6f

#define NTHREADS 512

#define Q2_STRIDE 260      // f2 stride, 260*2 % 32 == 8 -> conflict-free LDS.64
#define P2_STRIDE 68       // f2 stride, 68*2 % 32 == 8 (reads conflict-free)

#define Q2_F2 (32*Q2_STRIDE)          // 8320 f2
#define KS_FLOATS (BN*DDIM)           // 16384 floats per buffer
#define P2_F2 (32*P2_STRIDE)          // 2176 f2
#define SMEM_FLOATS (2*Q2_F2 + 2*KS_FLOATS + 2*P2_F2 + 4*BM)
#define SMEM_BYTES  (SMEM_FLOATS*4)   // ~216 KB

// d-paired, tf32-rounded copy of q: f2 slot s of row r = (q[r][k_s], q[r][k_s+4]),
// k_s = (s>>2)*8 + (s&3)
__device__ float  g_qtf[(size_t)NROWS*DDIM];
__device__ float2 g_qt[NROWS];        // (||q||^2, 1/t)

__device__ __forceinline__ float f2tf32f(float x) {
    unsigned r;
    asm("cvt.rna.tf32.f32 %0, %1;" : "=r"(r) : "f"(x));
    return __uint_as_float(r);
}
__device__ __forceinline__ float flg2(float x) {
    float r; asm("lg2.approx.f32 %0, %1;" : "=f"(r) : "f"(x)); return r;
}
__device__ __forceinline__ float fex2(float x) {
    float r; asm("ex2.approx.f32 %0, %1;" : "=f"(r) : "f"(x)); return r;
}

__device__ __forceinline__ void mma_tf32(float d[4],
    unsigned a0, unsigned a1, unsigned a2, unsigned a3,
    unsigned b0, unsigned b1) {
    asm volatile(
        "mma.sync.aligned.m16n8k8.row.col.f32.tf32.tf32.f32 "
        "{%0,%1,%2,%3}, {%4,%5,%6,%7}, {%8,%9}, {%0,%1,%2,%3};\n"
        : "+f"(d[0]), "+f"(d[1]), "+f"(d[2]), "+f"(d[3])
        : "r"(a0), "r"(a1), "r"(a2), "r"(a3), "r"(b0), "r"(b1));
}

// ---------------- prep: tf32 + d-paired copy + row stats ----------------
__global__ void prep_kernel(const float* __restrict__ q, const float* __restrict__ cp) {
    int row  = blockIdx.x * 8 + (threadIdx.x >> 5);
    int lane = threadIdx.x & 31;      // = k-group (8 d's each)
    const float4* qr = (const float4*)(q + (size_t)row * DDIM);
    float4 A = qr[lane * 2];          // d = 8*lane .. +3
    float4 B = qr[lane * 2 + 1];      // d = 8*lane+4 .. +7
    float s = A.x*A.x + A.y*A.y + A.z*A.z + A.w*A.w
            + B.x*B.x + B.y*B.y + B.z*B.z + B.w*B.w;
    A = make_float4(f2tf32f(A.x), f2tf32f(A.y), f2tf32f(A.z), f2tf32f(A.w));
    B = make_float4(f2tf32f(B.x), f2tf32f(B.y), f2tf32f(B.z), f2tf32f(B.w));
    float4* wr = (float4*)(g_qtf + (size_t)row * DDIM + lane * 8);
    wr[0] = make_float4(A.x, B.x, A.y, B.y);   // f2 slots 4l, 4l+1
    wr[1] = make_float4(A.z, B.z, A.w, B.w);   // f2 slots 4l+2, 4l+3
#pragma unroll
    for (int o = 16; o > 0; o >>= 1) s += __shfl_xor_sync(0xffffffffu, s, o);
    if (lane == 0) {
        float cc = fmaxf(*cp, EPSF);
        g_qt[row] = make_float2(s, 1.0f / fmaxf(1.0f - cc * s, EPSF));
    }
}

__device__ __forceinline__ float pcalc(float s, float qni, float coef, float qnj, float kf) {
    float diff = fmaxf(qni + qnj - 2.0f * s, 0.0f);
    float arg  = fmaf(coef, diff, 1.0f);
    arg = fmaxf(arg, 1.0f + EPSF) + EPSF;
    float x = arg - 1.0f;
    float y = arg + sqrtf(x * (arg + 1.0f));
    return fex2(-kf * flg2(y));
}

__global__ __launch_bounds__(NTHREADS, 1)
void hyp_attn_kernel(const float* __restrict__ cp, float* __restrict__ out) {
    extern __shared__ float smem[];
    float2* Q2  = (float2*)smem;                        // [32][Q2_STRIDE] row-paired
    float*  Ks  = smem + 2 * Q2_F2;                     // 2 x [64][256] d-paired+swz
    float2* P2  = (float2*)(Ks + 2 * KS_FLOATS);        // [32][P2_STRIDE] row-paired
    float*  lred = (float*)(P2 + P2_F2);                // [4][BM]

    uint32_t smem_u32;
    asm("{ .reg .u64 t; cvta.to.shared.u64 t, %1; cvt.u32.u64 %0, t; }"
        : "=r"(smem_u32) : "l"(smem));
    const uint32_t ks_u32 = smem_u32 + 2 * Q2_F2 * 4;

    const int tid  = threadIdx.x;
    const int w    = tid >> 5;      // 0..15
    const int lane = tid & 31;
    const int g    = lane >> 2;
    const int tg   = lane & 3;
    const int g3   = g & 3;
    const int ghi  = g >> 2;        // 0/1

    const float cc    = fmaxf(*cp, EPSF);
    const float two_c = 2.0f * cc;
    const float kf    = 1.0f / sqrtf(cc);

    const int rowbase = blockIdx.x * BM;

    // GEMM1: 4(m-quad) x 4(n) warps; warp tile 16x16 of S
    const int wm = w >> 2;          // quad id; also GEMM2 m-strip
    const int wn = w & 3;
    const int lr0 = wm * 16 + g;
    const int lr1 = lr0 + 8;
    const float2 qt0 = g_qt[rowbase + lr0];
    const float2 qt1 = g_qt[rowbase + lr1];
    const float qni0 = qt0.x, qni1 = qt1.x;
    const float tc0  = two_c * qt0.y;
    const float tc1  = two_c * qt1.y;
    const int grow0 = rowbase + lr0;
    const int grow1 = rowbase + lr1;

    // GEMM2: same m-strip (wm), n-chunk wn*64
    const int w8 = wn * 8;             // (col>>3) base for GEMM2 B
    const int g21c = (g3 << 1) | ghi;  // float-offset decoding col within 8-block

    // ---- prologue: build row-paired Q'' from d-paired g_qtf ----
    {
        // 32 pair-rows x 64 float4-groups = 2048 tasks
#pragma unroll
        for (int i = 0; i < 4; i++) {
            int t  = tid + i * NTHREADS;
            int rp = t >> 6;            // pair row 0..31
            int m  = t & 63;            // float4 group
            int rA = ((rp >> 3) << 4) + (rp & 7);
            int rB = rA + 8;
            const float4* pA = (const float4*)(g_qtf + (((size_t)(rowbase + rA)) << 8));
            const float4* pB = (const float4*)(g_qtf + (((size_t)(rowbase + rB)) << 8));
            float4 X = pA[m];
            float4 Y = pB[m];
            // source slots 2m,2m+1 hold (qA[k0],qA[k0+4]),(qA[k0+1],qA[k0+1+4])
            int k0 = ((m >> 1) << 3) + ((2 * m) & 3);
            float4* dst0 = (float4*)(Q2 + rp * Q2_STRIDE + k0);
            float4* dst1 = (float4*)(Q2 + rp * Q2_STRIDE + k0 + 4);
            *dst0 = make_float4(X.x, Y.x, X.z, Y.z);   // f2 k0, k0+1
            *dst1 = make_float4(X.y, Y.y, X.w, Y.w);   // f2 k0+4, k0+5
        }
    }

    // ---- prologue: cp.async K(0) into buf0 (swizzle chunks by row) ----
    {
        const float* src0 = g_qtf;
#pragma unroll
        for (int i = 0; i < 8; i++) {
            int f  = tid + i * NTHREADS;
            int r  = f >> 6;
            int c  = f & 63;
            int cs = c ^ (2 * (r & 3));
            uint32_t dst = ks_u32 + (r << 10) + (cs << 4);
            asm volatile("cp.async.cg.shared.global [%0], [%1], 16;\n"
                         :: "r"(dst), "l"(src0 + (r << 8) + (c << 2)) : "memory");
        }
        asm volatile("cp.async.commit_group;\n" ::: "memory");
    }

    float of[8][4];
#pragma unroll
    for (int nt = 0; nt < 8; nt++)
#pragma unroll
        for (int e = 0; e < 4; e++) of[nt][e] = 0.0f;

    float rsum0 = 0.0f, rsum1 = 0.0f;

    const float2* Arow = Q2 + (wm * 8 + g) * Q2_STRIDE;
    const float2* Prow = P2 + (wm * 8 + g) * P2_STRIDE;
    float2* Pwr = P2 + (wm * 8 + g) * P2_STRIDE;

    for (int jt = 0; jt < NITER; jt++) {
        const int jbase = jt * BN;
        const float* Kb = Ks + (jt & 1) * KS_FLOATS;

        asm volatile("cp.async.wait_group 0;\n" ::: "memory");
        __syncthreads();   // B1: K(jt) ready; all GEMM2(jt-1) done

        if (jt + 1 < NITER) {
            const float* srcN = g_qtf + ((size_t)(jbase + BN) << 8);
            uint32_t base = ks_u32 + ((jt + 1) & 1) * (KS_FLOATS * 4);
#pragma unroll
            for (int i = 0; i < 8; i++) {
                int f  = tid + i * NTHREADS;
                int r  = f >> 6;
                int c  = f & 63;
                int cs = c ^ (2 * (r & 3));
                uint32_t dst = base + (r << 10) + (cs << 4);
                asm volatile("cp.async.cg.shared.global [%0], [%1], 16;\n"
                             :: "r"(dst), "l"(srcN + (r << 8) + (c << 2)) : "memory");
            }
            asm volatile("cp.async.commit_group;\n" ::: "memory");
        }

        // ---- GEMM1: S = Q.K^T (warp tile 16x16) ----
        float sf[2][4];
#pragma unroll
        for (int nt = 0; nt < 2; nt++)
#pragma unroll
            for (int e = 0; e < 4; e++) sf[nt][e] = 0.0f;

        const float2* Bp0 = (const float2*)(Kb + ((wn * 16 + 0 + g) << 8));
        const float2* Bp1 = (const float2*)(Kb + ((wn * 16 + 8 + g) << 8));
#pragma unroll 8
        for (int kg = 0; kg < 32; kg++) {
            float2 a01 = Arow[kg * 8 + tg];
            float2 a23 = Arow[kg * 8 + tg + 4];
            int slot = ((kg ^ g3) << 2) + tg;
            float2 b0 = Bp0[slot];
            float2 b1 = Bp1[slot];
            mma_tf32(sf[0], __float_as_uint(a01.x), __float_as_uint(a01.y),
                            __float_as_uint(a23.x), __float_as_uint(a23.y),
                            __float_as_uint(b0.x),  __float_as_uint(b0.y));
            mma_tf32(sf[1], __float_as_uint(a01.x), __float_as_uint(a01.y),
                            __float_as_uint(a23.x), __float_as_uint(a23.y),
                            __float_as_uint(b1.x),  __float_as_uint(b1.y));
        }

        // ---- transform: p = exp(-dist), accumulate l, store P (row-paired) ----
#pragma unroll
        for (int nt = 0; nt < 2; nt++) {
            const int cbase = wn * 16 + nt * 8 + tg * 2;
            const int col0  = jbase + cbase;
            float4 qq = *(const float4*)((const float*)&g_qt[col0]);
            float p00 = pcalc(sf[nt][0], qni0, tc0 * qq.y, qq.x, kf);
            float p01 = pcalc(sf[nt][1], qni0, tc0 * qq.w, qq.z, kf);
            float p10 = pcalc(sf[nt][2], qni1, tc1 * qq.y, qq.x, kf);
            float p11 = pcalc(sf[nt][3], qni1, tc1 * qq.w, qq.z, kf);
            if (col0     == grow0) p00 = 1.0f;
            if (col0 + 1 == grow0) p01 = 1.0f;
            if (col0     == grow1) p10 = 1.0f;
            if (col0 + 1 == grow1) p11 = 1.0f;
            rsum0 += p00 + p01;
            rsum1 += p10 + p11;
            *(float4*)(Pwr + cbase) = make_float4(
                f2tf32f(p00), f2tf32f(p10), f2tf32f(p01), f2tf32f(p11));
        }
        // quad-local barrier: only the 4 warps sharing this 16-row strip
        asm volatile("bar.sync %0, 128;\n" :: "r"(1 + wm) : "memory");

        // ---- GEMM2: O += P.V (warp tile 16x64) ----
#pragma unroll
        for (int kk = 0; kk < BN; kk += 8) {
            float2 a01 = Prow[kk + tg];
            float2 a23 = Prow[kk + tg + 4];
            unsigned a0 = __float_as_uint(a01.x), a1 = __float_as_uint(a01.y);
            unsigned a2 = __float_as_uint(a23.x), a3 = __float_as_uint(a23.y);
            const float* r0 = Kb + ((kk + tg) << 8);
            const float* r1 = Kb + ((kk + tg + 4) << 8);
#pragma unroll
            for (int nt = 0; nt < 8; nt++) {
                int off = ((w8 + nt) ^ tg) << 3;
                // both rows share the same chunk swizzle ((r&3)==tg), so the
                // in-row index is IDENTICAL for b0 and b1 (same output column)
                unsigned b0 = __float_as_uint(r0[off + g21c]);
                unsigned b1 = __float_as_uint(r1[off + g21c]);
                mma_tf32(of[nt], a0, a1, a2, a3, b0, b1);
            }
        }
        // no trailing barrier: next B1 (global) orders everything
    }

    // ---- reduce row sums (4 warp partials per row) ----
    rsum0 += __shfl_xor_sync(0xffffffffu, rsum0, 1);
    rsum0 += __shfl_xor_sync(0xffffffffu, rsum0, 2);
    rsum1 += __shfl_xor_sync(0xffffffffu, rsum1, 1);
    rsum1 += __shfl_xor_sync(0xffffffffu, rsum1, 2);
    if (tg == 0) { lred[wn * BM + lr0] = rsum0; lred[wn * BM + lr1] = rsum1; }
    __syncthreads();

    // ---- epilogue: O / l ----
    {
        const int r2 = wm * 16 + g;
        const float li0 = 1.0f / (lred[r2] + lred[BM + r2] +
                                  lred[2 * BM + r2] + lred[3 * BM + r2]);
        const float li1 = 1.0f / (lred[r2 + 8] + lred[BM + r2 + 8] +
                                  lred[2 * BM + r2 + 8] + lred[3 * BM + r2 + 8]);
        const int grA = rowbase + r2;
#pragma unroll
        for (int nt = 0; nt < 8; nt++) {
            const int col = wn * 64 + nt * 8 + tg * 2;
            *(float2*)(out + (size_t)grA * DDIM + col) =
                make_float2(of[nt][0] * li0, of[nt][1] * li0);
            *(float2*)(out + (size_t)(grA + 8) * DDIM + col) =
                make_float2(of[nt][2] * li1, of[nt][3] * li1);
        }
    }
}

extern "C" void kernel_launch(void* const* d_in, const int* in_sizes, int n_in,
                              void* d_out, int out_size) {
    const float* q  = (const float*)d_in[0];
    const float* cp = (const float*)d_in[1];
    float* out      = (float*)d_out;

    cudaFuncSetAttribute(hyp_attn_kernel,
                         cudaFuncAttributeMaxDynamicSharedMemorySize, SMEM_BYTES);

    prep_kernel<<<NROWS / 8, 256>>>(q, cp);
    hyp_attn_kernel<<<NROWS / BM, NTHREADS, SMEM_BYTES>>>(cp, out);
}

// round 9
// speedup vs baseline: 1.0205x; 1.0000x over previous
#include <cuda_runtime.h>
#include <cstdint>

#define NROWS 8192
#define DDIM  256
#define BM    64
#define BN    64
#define NITER (NROWS/BN)
#define EPSF  1e-6f

#define NTHREADS 512

#define Q2_STRIDE 260      // f2 stride, 260*2 % 32 == 8 -> conflict-free LDS.64
#define P2_STRIDE 68       // f2 stride, 68*2 % 32 == 8 (reads conflict-free)

#define Q2_F2 (32*Q2_STRIDE)          // 8320 f2
#define KS_FLOATS (BN*DDIM)           // 16384 floats per buffer
#define P2_F2 (32*P2_STRIDE)          // 2176 f2
#define SMEM_FLOATS (2*Q2_F2 + 2*KS_FLOATS + 2*P2_F2 + 4*BM)
#define SMEM_BYTES  (SMEM_FLOATS*4)   // ~216 KB

// d-paired, tf32-rounded copy of q: f2 slot s of row r = (q[r][k_s], q[r][k_s+4]),
// k_s = (s>>2)*8 + (s&3)
__device__ float  g_qtf[(size_t)NROWS*DDIM];
__device__ float2 g_qt[NROWS];        // (||q||^2, 1/t)

__device__ __forceinline__ float f2tf32f(float x) {
    unsigned r;
    asm("cvt.rna.tf32.f32 %0, %1;" : "=r"(r) : "f"(x));
    return __uint_as_float(r);
}
__device__ __forceinline__ float flg2(float x) {
    float r; asm("lg2.approx.f32 %0, %1;" : "=f"(r) : "f"(x)); return r;
}
__device__ __forceinline__ float fex2(float x) {
    float r; asm("ex2.approx.f32 %0, %1;" : "=f"(r) : "f"(x)); return r;
}

__device__ __forceinline__ void mma_tf32(float d[4],
    unsigned a0, unsigned a1, unsigned a2, unsigned a3,
    unsigned b0, unsigned b1) {
    asm volatile(
        "mma.sync.aligned.m16n8k8.row.col.f32.tf32.tf32.f32 "
        "{%0,%1,%2,%3}, {%4,%5,%6,%7}, {%8,%9}, {%0,%1,%2,%3};\n"
        : "+f"(d[0]), "+f"(d[1]), "+f"(d[2]), "+f"(d[3])
        : "r"(a0), "r"(a1), "r"(a2), "r"(a3), "r"(b0), "r"(b1));
}

// ---------------- prep: tf32 + d-paired copy + row stats ----------------
__global__ void prep_kernel(const float* __restrict__ q, const float* __restrict__ cp) {
    int row  = blockIdx.x * 8 + (threadIdx.x >> 5);
    int lane = threadIdx.x & 31;      // = k-group (8 d's each)
    const float4* qr = (const float4*)(q + (size_t)row * DDIM);
    float4 A = qr[lane * 2];          // d = 8*lane .. +3
    float4 B = qr[lane * 2 + 1];      // d = 8*lane+4 .. +7
    float s = A.x*A.x + A.y*A.y + A.z*A.z + A.w*A.w
            + B.x*B.x + B.y*B.y + B.z*B.z + B.w*B.w;
    A = make_float4(f2tf32f(A.x), f2tf32f(A.y), f2tf32f(A.z), f2tf32f(A.w));
    B = make_float4(f2tf32f(B.x), f2tf32f(B.y), f2tf32f(B.z), f2tf32f(B.w));
    float4* wr = (float4*)(g_qtf + (size_t)row * DDIM + lane * 8);
    wr[0] = make_float4(A.x, B.x, A.y, B.y);   // f2 slots 4l, 4l+1
    wr[1] = make_float4(A.z, B.z, A.w, B.w);   // f2 slots 4l+2, 4l+3
#pragma unroll
    for (int o = 16; o > 0; o >>= 1) s += __shfl_xor_sync(0xffffffffu, s, o);
    if (lane == 0) {
        float cc = fmaxf(*cp, EPSF);
        g_qt[row] = make_float2(s, 1.0f / fmaxf(1.0f - cc * s, EPSF));
    }
}

__device__ __forceinline__ float pcalc(float s, float qni, float coef, float qnj, float kf) {
    float diff = fmaxf(qni + qnj - 2.0f * s, 0.0f);
    float arg  = fmaf(coef, diff, 1.0f);
    arg = fmaxf(arg, 1.0f + EPSF) + EPSF;
    float x = arg - 1.0f;
    float y = arg + sqrtf(x * (arg + 1.0f));
    return fex2(-kf * flg2(y));
}

__global__ __launch_bounds__(NTHREADS, 1)
void hyp_attn_kernel(const float* __restrict__ cp, float* __restrict__ out) {
    extern __shared__ float smem[];
    float2* Q2  = (float2*)smem;                        // [32][Q2_STRIDE] row-paired
    float*  Ks  = smem + 2 * Q2_F2;                     // 2 x [64][256] d-paired+swz
    float2* P2  = (float2*)(Ks + 2 * KS_FLOATS);        // [32][P2_STRIDE] row-paired
    float*  lred = (float*)(P2 + P2_F2);                // [4][BM]

    uint32_t smem_u32;
    asm("{ .reg .u64 t; cvta.to.shared.u64 t, %1; cvt.u32.u64 %0, t; }"
        : "=r"(smem_u32) : "l"(smem));
    const uint32_t ks_u32 = smem_u32 + 2 * Q2_F2 * 4;

    const int tid  = threadIdx.x;
    const int w    = tid >> 5;      // 0..15
    const int lane = tid & 31;
    const int g    = lane >> 2;
    const int tg   = lane & 3;
    const int g3   = g & 3;
    const int ghi  = g >> 2;        // 0/1

    const float cc    = fmaxf(*cp, EPSF);
    const float two_c = 2.0f * cc;
    const float kf    = 1.0f / sqrtf(cc);

    const int rowbase = blockIdx.x * BM;

    // GEMM1: 4(m-quad) x 4(n) warps; warp tile 16x16 of S
    const int wm = w >> 2;          // quad id; also GEMM2 m-strip
    const int wn = w & 3;
    const int lr0 = wm * 16 + g;
    const int lr1 = lr0 + 8;
    const float2 qt0 = g_qt[rowbase + lr0];
    const float2 qt1 = g_qt[rowbase + lr1];
    const float qni0 = qt0.x, qni1 = qt1.x;
    const float tc0  = two_c * qt0.y;
    const float tc1  = two_c * qt1.y;
    const int grow0 = rowbase + lr0;
    const int grow1 = rowbase + lr1;

    // GEMM2: same m-strip (wm), n-chunk wn*64
    const int w8 = wn * 8;             // (col>>3) base for GEMM2 B
    const int g21c = (g3 << 1) | ghi;  // float-offset decoding col within 8-block

    // ---- prologue: build row-paired Q'' from d-paired g_qtf ----
    {
        // 32 pair-rows x 64 float4-groups = 2048 tasks
#pragma unroll
        for (int i = 0; i < 4; i++) {
            int t  = tid + i * NTHREADS;
            int rp = t >> 6;            // pair row 0..31
            int m  = t & 63;            // float4 group
            int rA = ((rp >> 3) << 4) + (rp & 7);
            int rB = rA + 8;
            const float4* pA = (const float4*)(g_qtf + (((size_t)(rowbase + rA)) << 8));
            const float4* pB = (const float4*)(g_qtf + (((size_t)(rowbase + rB)) << 8));
            float4 X = pA[m];
            float4 Y = pB[m];
            // source slots 2m,2m+1 hold (qA[k0],qA[k0+4]),(qA[k0+1],qA[k0+1+4])
            int k0 = ((m >> 1) << 3) + ((2 * m) & 3);
            float4* dst0 = (float4*)(Q2 + rp * Q2_STRIDE + k0);
            float4* dst1 = (float4*)(Q2 + rp * Q2_STRIDE + k0 + 4);
            *dst0 = make_float4(X.x, Y.x, X.z, Y.z);   // f2 k0, k0+1
            *dst1 = make_float4(X.y, Y.y, X.w, Y.w);   // f2 k0+4, k0+5
        }
    }

    // ---- prologue: cp.async K(0) into buf0 (swizzle chunks by row) ----
    {
        const float* src0 = g_qtf;
#pragma unroll
        for (int i = 0; i < 8; i++) {
            int f  = tid + i * NTHREADS;
            int r  = f >> 6;
            int c  = f & 63;
            int cs = c ^ (2 * (r & 3));
            uint32_t dst = ks_u32 + (r << 10) + (cs << 4);
            asm volatile("cp.async.cg.shared.global [%0], [%1], 16;\n"
                         :: "r"(dst), "l"(src0 + (r << 8) + (c << 2)) : "memory");
        }
        asm volatile("cp.async.commit_group;\n" ::: "memory");
    }

    float of[8][4];
#pragma unroll
    for (int nt = 0; nt < 8; nt++)
#pragma unroll
        for (int e = 0; e < 4; e++) of[nt][e] = 0.0f;

    float rsum0 = 0.0f, rsum1 = 0.0f;

    const float2* Arow = Q2 + (wm * 8 + g) * Q2_STRIDE;
    const float2* Prow = P2 + (wm * 8 + g) * P2_STRIDE;
    float2* Pwr = P2 + (wm * 8 + g) * P2_STRIDE;

    for (int jt = 0; jt < NITER; jt++) {
        const int jbase = jt * BN;
        const float* Kb = Ks + (jt & 1) * KS_FLOATS;

        asm volatile("cp.async.wait_group 0;\n" ::: "memory");
        __syncthreads();   // B1: K(jt) ready; all GEMM2(jt-1) done

        if (jt + 1 < NITER) {
            const float* srcN = g_qtf + ((size_t)(jbase + BN) << 8);
            uint32_t base = ks_u32 + ((jt + 1) & 1) * (KS_FLOATS * 4);
#pragma unroll
            for (int i = 0; i < 8; i++) {
                int f  = tid + i * NTHREADS;
                int r  = f >> 6;
                int c  = f & 63;
                int cs = c ^ (2 * (r & 3));
                uint32_t dst = base + (r << 10) + (cs << 4);
                asm volatile("cp.async.cg.shared.global [%0], [%1], 16;\n"
                             :: "r"(dst), "l"(srcN + (r << 8) + (c << 2)) : "memory");
            }
            asm volatile("cp.async.commit_group;\n" ::: "memory");
        }

        // ---- GEMM1: S = Q.K^T (warp tile 16x16) ----
        float sf[2][4];
#pragma unroll
        for (int nt = 0; nt < 2; nt++)
#pragma unroll
            for (int e = 0; e < 4; e++) sf[nt][e] = 0.0f;

        const float2* Bp0 = (const float2*)(Kb + ((wn * 16 + 0 + g) << 8));
        const float2* Bp1 = (const float2*)(Kb + ((wn * 16 + 8 + g) << 8));
#pragma unroll 8
        for (int kg = 0; kg < 32; kg++) {
            float2 a01 = Arow[kg * 8 + tg];
            float2 a23 = Arow[kg * 8 + tg + 4];
            int slot = ((kg ^ g3) << 2) + tg;
            float2 b0 = Bp0[slot];
            float2 b1 = Bp1[slot];
            mma_tf32(sf[0], __float_as_uint(a01.x), __float_as_uint(a01.y),
                            __float_as_uint(a23.x), __float_as_uint(a23.y),
                            __float_as_uint(b0.x),  __float_as_uint(b0.y));
            mma_tf32(sf[1], __float_as_uint(a01.x), __float_as_uint(a01.y),
                            __float_as_uint(a23.x), __float_as_uint(a23.y),
                            __float_as_uint(b1.x),  __float_as_uint(b1.y));
        }

        // ---- transform: p = exp(-dist), accumulate l, store P (row-paired) ----
#pragma unroll
        for (int nt = 0; nt < 2; nt++) {
            const int cbase = wn * 16 + nt * 8 + tg * 2;
            const int col0  = jbase + cbase;
            float4 qq = *(const float4*)((const float*)&g_qt[col0]);
            float p00 = pcalc(sf[nt][0], qni0, tc0 * qq.y, qq.x, kf);
            float p01 = pcalc(sf[nt][1], qni0, tc0 * qq.w, qq.z, kf);
            float p10 = pcalc(sf[nt][2], qni1, tc1 * qq.y, qq.x, kf);
            float p11 = pcalc(sf[nt][3], qni1, tc1 * qq.w, qq.z, kf);
            if (col0     == grow0) p00 = 1.0f;
            if (col0 + 1 == grow0) p01 = 1.0f;
            if (col0     == grow1) p10 = 1.0f;
            if (col0 + 1 == grow1) p11 = 1.0f;
            rsum0 += p00 + p01;
            rsum1 += p10 + p11;
            *(float4*)(Pwr + cbase) = make_float4(
                f2tf32f(p00), f2tf32f(p10), f2tf32f(p01), f2tf32f(p11));
        }
        // quad-local barrier: only the 4 warps sharing this 16-row strip
        asm volatile("bar.sync %0, 128;\n" :: "r"(1 + wm) : "memory");

        // ---- GEMM2: O += P.V (warp tile 16x64) ----
#pragma unroll
        for (int kk = 0; kk < BN; kk += 8) {
            float2 a01 = Prow[kk + tg];
            float2 a23 = Prow[kk + tg + 4];
            unsigned a0 = __float_as_uint(a01.x), a1 = __float_as_uint(a01.y);
            unsigned a2 = __float_as_uint(a23.x), a3 = __float_as_uint(a23.y);
            const float* r0 = Kb + ((kk + tg) << 8);
            const float* r1 = Kb + ((kk + tg + 4) << 8);
#pragma unroll
            for (int nt = 0; nt < 8; nt++) {
                int off = ((w8 + nt) ^ tg) << 3;
                // both rows share the same chunk swizzle ((r&3)==tg), so the
                // in-row index is IDENTICAL for b0 and b1 (same output column)
                unsigned b0 = __float_as_uint(r0[off + g21c]);
                unsigned b1 = __float_as_uint(r1[off + g21c]);
                mma_tf32(of[nt], a0, a1, a2, a3, b0, b1);
            }
        }
        // no trailing barrier: next B1 (global) orders everything
    }

    // ---- reduce row sums (4 warp partials per row) ----
    rsum0 += __shfl_xor_sync(0xffffffffu, rsum0, 1);
    rsum0 += __shfl_xor_sync(0xffffffffu, rsum0, 2);
    rsum1 += __shfl_xor_sync(0xffffffffu, rsum1, 1);
    rsum1 += __shfl_xor_sync(0xffffffffu, rsum1, 2);
    if (tg == 0) { lred[wn * BM + lr0] = rsum0; lred[wn * BM + lr1] = rsum1; }
    __syncthreads();

    // ---- epilogue: O / l ----
    {
        const int r2 = wm * 16 + g;
        const float li0 = 1.0f / (lred[r2] + lred[BM + r2] +
                                  lred[2 * BM + r2] + lred[3 * BM + r2]);
        const float li1 = 1.0f / (lred[r2 + 8] + lred[BM + r2 + 8] +
                                  lred[2 * BM + r2 + 8] + lred[3 * BM + r2 + 8]);
        const int grA = rowbase + r2;
#pragma unroll
        for (int nt = 0; nt < 8; nt++) {
            const int col = wn * 64 + nt * 8 + tg * 2;
            *(float2*)(out + (size_t)grA * DDIM + col) =
                make_float2(of[nt][0] * li0, of[nt][1] * li0);
            *(float2*)(out + (size_t)(grA + 8) * DDIM + col) =
                make_float2(of[nt][2] * li1, of[nt][3] * li1);
        }
    }
}

extern "C" void kernel_launch(void* const* d_in, const int* in_sizes, int n_in,
                              void* d_out, int out_size) {
    const float* q  = (const float*)d_in[0];
    const float* cp = (const float*)d_in[1];
    float* out      = (float*)d_out;

    cudaFuncSetAttribute(hyp_attn_kernel,
                         cudaFuncAttributeMaxDynamicSharedMemorySize, SMEM_BYTES);

    prep_kernel<<<NROWS / 8, 256>>>(q, cp);
    hyp_attn_kernel<<<NROWS / BM, NTHREADS, SMEM_BYTES>>>(cp, out);
}

// round 11
// speedup vs baseline: 1.6764x; 1.6426x over previous
#include <cuda_runtime.h>
#include <cuda_fp16.h>
#include <cstdint>

#define NROWS 8192
#define DDIM  256
#define BM    128
#define BN    64
#define NIT   64              // 4096 keys per CTA / 64
#define EPSF  1e-6f
#define NTHREADS 256

// shared-memory layout in 32-bit WORDS
#define QW 132                // Q row stride (words)  132 % 32 == 4 -> conflict-free
#define KW 132                // K row stride (words)
#define VW 36                 // V^T row stride (words) 36 % 32 == 4
#define QOFF    0
#define KOFF(b) (16896 + 8448*(b))     // 128*132 .. two 64*132 buffers
#define VOFF(b) (33792 + 9216*(b))     // two 256*36 buffers
#define STOFF(b) (52224 + 128*(b))     // 64 float2 stats per buffer
#define SMEM_WORDS 52480
#define SMEM_TOTAL (SMEM_WORDS*4)      // 209920 B

__device__ __half g_qh [(size_t)NROWS*DDIM];   // half copy, row-major [row][d]
__device__ __half g_qhT[(size_t)DDIM*NROWS];   // half copy, transposed [d][row]
__device__ float2 g_qt[NROWS];                 // (||q||^2, 1/t)
__device__ float  g_opart[(size_t)128*BM*DDIM];
__device__ float  g_lpart[128*BM];

__device__ __forceinline__ float flg2(float x) {
    float r; asm("lg2.approx.f32 %0, %1;" : "=f"(r) : "f"(x)); return r;
}
__device__ __forceinline__ float fex2(float x) {
    float r; asm("ex2.approx.f32 %0, %1;" : "=f"(r) : "f"(x)); return r;
}
__device__ __forceinline__ uint32_t pack_h2(float lo, float hi) {
    __half2 h = __floats2half2_rn(lo, hi);     // .x = lo -> low 16 bits
    uint32_t u; __builtin_memcpy(&u, &h, 4); return u;
}
__device__ __forceinline__ void hmma(float d[4],
    uint32_t a0, uint32_t a1, uint32_t a2, uint32_t a3,
    uint32_t b0, uint32_t b1) {
    asm volatile(
        "mma.sync.aligned.m16n8k16.row.col.f32.f16.f16.f32 "
        "{%0,%1,%2,%3}, {%4,%5,%6,%7}, {%8,%9}, {%0,%1,%2,%3};\n"
        : "+f"(d[0]), "+f"(d[1]), "+f"(d[2]), "+f"(d[3])
        : "r"(a0), "r"(a1), "r"(a2), "r"(a3), "r"(b0), "r"(b1));
}
__device__ __forceinline__ void cpa16(uint32_t dst, const void* src) {
    asm volatile("cp.async.cg.shared.global [%0], [%1], 16;"
                 :: "r"(dst), "l"(src) : "memory");
}
#define CPA_COMMIT() asm volatile("cp.async.commit_group;" ::: "memory")
#define CPA_WAIT0()  asm volatile("cp.async.wait_group 0;" ::: "memory")

// ---------------- prep: half copies (both layouts) + row stats ----------------
__global__ void prep_kernel(const float* __restrict__ q, const float* __restrict__ cp) {
    int row  = blockIdx.x * 8 + (threadIdx.x >> 5);
    int lane = threadIdx.x & 31;          // handles d = 8*lane .. 8*lane+7
    const float4* qr = (const float4*)(q + (size_t)row * DDIM);
    float4 A = qr[lane * 2], B = qr[lane * 2 + 1];
    __half h[8];
    h[0]=__float2half_rn(A.x); h[1]=__float2half_rn(A.y);
    h[2]=__float2half_rn(A.z); h[3]=__float2half_rn(A.w);
    h[4]=__float2half_rn(B.x); h[5]=__float2half_rn(B.y);
    h[6]=__float2half_rn(B.z); h[7]=__float2half_rn(B.w);
    float s = 0.0f;
#pragma unroll
    for (int i = 0; i < 8; i++) { float r = __half2float(h[i]); s += r * r; }
    // row-major
    uint32_t* wr = (uint32_t*)(g_qh + (size_t)row * DDIM + lane * 8);
#pragma unroll
    for (int i = 0; i < 4; i++) {
        __half2 p = __halves2half2(h[2*i], h[2*i+1]);
        uint32_t u; __builtin_memcpy(&u, &p, 4); wr[i] = u;
    }
    // transposed
    int d0 = lane * 8;
#pragma unroll
    for (int i = 0; i < 8; i++)
        g_qhT[(size_t)(d0 + i) * NROWS + row] = h[i];
#pragma unroll
    for (int o = 16; o > 0; o >>= 1) s += __shfl_xor_sync(0xffffffffu, s, o);
    if (lane == 0) {
        float cc = fmaxf(*cp, EPSF);
        g_qt[row] = make_float2(s, 1.0f / fmaxf(1.0f - cc * s, EPSF));
    }
}

__device__ __forceinline__ float pcalc(float s, float qni, float coef,
                                       float qnj, float kf) {
    float diff = fmaxf(qni + qnj - 2.0f * s, 0.0f);
    float arg  = fmaf(coef, diff, 1.0f);
    arg = fmaxf(arg, 1.0f + EPSF) + EPSF;
    float x = arg - 1.0f;
    float y = arg + sqrtf(x * (arg + 1.0f));
    return fex2(-kf * flg2(y));
}

__device__ __forceinline__ void prefetch_tile(uint32_t su, int tid, int kb, int b) {
    // K tile: 64 rows x 32 chunks (16B)
#pragma unroll
    for (int i = 0; i < 8; i++) {
        int f = tid + i * NTHREADS;
        int r = f >> 5, c = f & 31;
        cpa16(su + (KOFF(b) + r * KW + c * 4) * 4,
              g_qh + ((size_t)(kb + r) << 8) + c * 8);
    }
    // V^T tile: 256 rows x 8 chunks
#pragma unroll
    for (int i = 0; i < 8; i++) {
        int f = tid + i * NTHREADS;
        int r = f >> 3, c = f & 7;
        cpa16(su + (VOFF(b) + r * VW + c * 4) * 4,
              g_qhT + (size_t)r * NROWS + kb + c * 8);
    }
    // stats: 64 float2 = 32 chunks
    if (tid < 32)
        cpa16(su + (STOFF(b) + tid * 4) * 4, (const float*)(g_qt + kb) + tid * 4);
    CPA_COMMIT();
}

// ---------------- main kernel: fp16 flash-style, P in registers ----------------
__global__ void __launch_bounds__(NTHREADS, 1)
hyp_fa_kernel(const float* __restrict__ cp) {
    extern __shared__ uint32_t sw[];
    uint32_t su;
    asm("{ .reg .u64 t; cvta.to.shared.u64 t, %1; cvt.u32.u64 %0, t; }"
        : "=r"(su) : "l"(sw));

    const int tid  = threadIdx.x;
    const int w    = tid >> 5;            // 0..7, owns rows [16w, 16w+16)
    const int lane = tid & 31;
    const int g    = lane >> 2;
    const int tg   = lane & 3;
    const int bid  = blockIdx.x;
    const int qb   = bid >> 1;
    const int keybase = (bid & 1) * (NROWS / 2);
    const int wbase = w * 16;

    const float ccv = fmaxf(*cp, EPSF);
    const float kf  = 1.0f / sqrtf(ccv);

    // ---- prologue: Q tile + first K/V tile ----
#pragma unroll
    for (int i = 0; i < 16; i++) {
        int f = tid + i * NTHREADS;
        int r = f >> 5, c = f & 31;
        cpa16(su + (QOFF + r * QW + c * 4) * 4,
              g_qh + ((size_t)(qb * BM + r) << 8) + c * 8);
    }
    prefetch_tile(su, tid, keybase, 0);
    CPA_WAIT0();
    __syncthreads();

    const int gr0 = qb * BM + wbase + g;
    const int gr1 = gr0 + 8;
    const float2 qt0 = g_qt[gr0], qt1 = g_qt[gr1];
    const float qni0 = qt0.x, qni1 = qt1.x;
    const float tc0 = 2.0f * ccv * qt0.y;
    const float tc1 = 2.0f * ccv * qt1.y;

    const uint32_t* Aw0 = sw + QOFF + (wbase + g) * QW;
    const uint32_t* Aw1 = Aw0 + 8 * QW;

    float of[32][4];
#pragma unroll
    for (int n = 0; n < 32; n++)
#pragma unroll
        for (int e = 0; e < 4; e++) of[n][e] = 0.0f;
    float rsum0 = 0.0f, rsum1 = 0.0f;

    for (int jt = 0; jt < NIT; jt++) {
        const int b = jt & 1;
        CPA_WAIT0();
        __syncthreads();                       // buf b ready; prev reads done
        if (jt + 1 < NIT)
            prefetch_tile(su, tid, keybase + (jt + 1) * BN, b ^ 1);

        // ---- GEMM1: S(16x64) = Q(16x256) . K^T ----
        float sf[8][4];
#pragma unroll
        for (int n = 0; n < 8; n++)
#pragma unroll
            for (int e = 0; e < 4; e++) sf[n][e] = 0.0f;
        const uint32_t* Kb = sw + KOFF(b);
#pragma unroll
        for (int ks = 0; ks < 16; ks++) {
            uint32_t a0 = Aw0[8 * ks + tg];
            uint32_t a1 = Aw1[8 * ks + tg];
            uint32_t a2 = Aw0[8 * ks + tg + 4];
            uint32_t a3 = Aw1[8 * ks + tg + 4];
#pragma unroll
            for (int nb = 0; nb < 8; nb++) {
                const uint32_t* Br = Kb + (nb * 8 + g) * KW + 8 * ks;
                hmma(sf[nb], a0, a1, a2, a3, Br[tg], Br[tg + 4]);
            }
        }

        // ---- transform: p = exp(-dist); P stays in registers (fp16) ----
        const float* st = (const float*)(sw + STOFF(b));
        const int j0 = keybase + jt * BN;
        uint32_t ph0[8], ph1[8];
#pragma unroll
        for (int nb = 0; nb < 8; nb++) {
            const int c0i = nb * 8 + 2 * tg;
            float4 qq = *(const float4*)(st + c0i * 2);  // (qn,ti, qn,ti)
            float p00 = pcalc(sf[nb][0], qni0, tc0 * qq.y, qq.x, kf);
            float p01 = pcalc(sf[nb][1], qni0, tc0 * qq.w, qq.z, kf);
            float p10 = pcalc(sf[nb][2], qni1, tc1 * qq.y, qq.x, kf);
            float p11 = pcalc(sf[nb][3], qni1, tc1 * qq.w, qq.z, kf);
            if (j0 + c0i     == gr0) p00 = 1.0f;         // exact diagonal
            if (j0 + c0i + 1 == gr0) p01 = 1.0f;
            if (j0 + c0i     == gr1) p10 = 1.0f;
            if (j0 + c0i + 1 == gr1) p11 = 1.0f;
            rsum0 += p00 + p01;
            rsum1 += p10 + p11;
            ph0[nb] = pack_h2(p00, p01);
            ph1[nb] = pack_h2(p10, p11);
        }

        // ---- GEMM2: O(16x256) += P(16x64) . V ; A from registers, B = V^T ----
        const uint32_t* Vb = sw + VOFF(b);
#pragma unroll
        for (int ks2 = 0; ks2 < 4; ks2++) {
            uint32_t a0 = ph0[2 * ks2],     a1 = ph1[2 * ks2];
            uint32_t a2 = ph0[2 * ks2 + 1], a3 = ph1[2 * ks2 + 1];
#pragma unroll
            for (int nb2 = 0; nb2 < 32; nb2++) {
                const uint32_t* Vr = Vb + (nb2 * 8 + g) * VW + 8 * ks2;
                hmma(of[nb2], a0, a1, a2, a3, Vr[tg], Vr[tg + 4]);
            }
        }
    }

    // ---- reduce row sums over tg ----
    rsum0 += __shfl_xor_sync(0xffffffffu, rsum0, 1);
    rsum0 += __shfl_xor_sync(0xffffffffu, rsum0, 2);
    rsum1 += __shfl_xor_sync(0xffffffffu, rsum1, 1);
    rsum1 += __shfl_xor_sync(0xffffffffu, rsum1, 2);

    // ---- epilogue: write O and l partials ----
    float* op0 = g_opart + ((size_t)bid << 15) + (size_t)(wbase + g) * DDIM;
    float* op1 = op0 + 8 * DDIM;
#pragma unroll
    for (int nb2 = 0; nb2 < 32; nb2++) {
        const int col = nb2 * 8 + 2 * tg;
        *(float2*)(op0 + col) = make_float2(of[nb2][0], of[nb2][1]);
        *(float2*)(op1 + col) = make_float2(of[nb2][2], of[nb2][3]);
    }
    if (tg == 0) {
        g_lpart[bid * BM + wbase + g]     = rsum0;
        g_lpart[bid * BM + wbase + g + 8] = rsum1;
    }
}

// ---------------- combine: out = (O0+O1)/(l0+l1) ----------------
__global__ void combine_kernel(float* __restrict__ out) {
    int idx = blockIdx.x * 256 + threadIdx.x;     // over 524288 float4s
    int r  = idx >> 6, c4 = idx & 63;
    int qb = r >> 7, lr = r & 127;
    float l = g_lpart[(2*qb) * BM + lr] + g_lpart[(2*qb + 1) * BM + lr];
    float inv = 1.0f / l;
    const float4* o0 = (const float4*)(g_opart + ((size_t)(2*qb)     << 15) + ((size_t)lr << 8));
    const float4* o1 = (const float4*)(g_opart + ((size_t)(2*qb + 1) << 15) + ((size_t)lr << 8));
    float4 a = o0[c4], b = o1[c4];
    ((float4*)out)[idx] = make_float4((a.x + b.x) * inv, (a.y + b.y) * inv,
                                      (a.z + b.z) * inv, (a.w + b.w) * inv);
}

extern "C" void kernel_launch(void* const* d_in, const int* in_sizes, int n_in,
                              void* d_out, int out_size) {
    const float* q  = (const float*)d_in[0];
    const float* cp = (const float*)d_in[1];
    float* out      = (float*)d_out;

    cudaFuncSetAttribute(hyp_fa_kernel,
                         cudaFuncAttributeMaxDynamicSharedMemorySize, SMEM_TOTAL);

    prep_kernel<<<NROWS / 8, 256>>>(q, cp);
    hyp_fa_kernel<<<128, NTHREADS, SMEM_TOTAL>>>(cp);
    combine_kernel<<<2048, 256>>>(out);
}

// round 12
// speedup vs baseline: 1.8946x; 1.1302x over previous
#include <cuda_runtime.h>
#include <cuda_fp16.h>
#include <cstdint>

#define NROWS 8192
#define DDIM  256
#define BM    128
#define BN    64
#define NIT   64              // 4096 keys per CTA / 64
#define EPSF  1e-6f
#define NTHREADS 256

// shared-memory layout in 32-bit WORDS
#define QW 132                // Q row stride (words): 132 % 32 == 4 -> conflict-free
#define KW 132                // K row stride (words)
#define QOFF     0
#define KOFF(b)  (16896 + 8448*(b))    // two 64x132 K buffers
#define STOFF(b) (33792 + 128*(b))     // 64 float2 stats per buffer
#define SMEM_WORDS 34304
#define SMEM_TOTAL (SMEM_WORDS*4)      // 137216 B

#define KROWB 528                      // K/Q row stride in bytes
#define KBUFB 33792                    // K buffer stride in bytes

__device__ __half g_qh[(size_t)NROWS*DDIM];    // half copy, row-major [row][d]
__device__ float2 g_qt[NROWS];                 // (||q||^2, 1/t)
__device__ float  g_opart[(size_t)128*BM*DDIM];
__device__ float  g_lpart[128*BM];

__device__ __forceinline__ float flg2(float x) {
    float r; asm("lg2.approx.f32 %0, %1;" : "=f"(r) : "f"(x)); return r;
}
__device__ __forceinline__ float fex2(float x) {
    float r; asm("ex2.approx.f32 %0, %1;" : "=f"(r) : "f"(x)); return r;
}
__device__ __forceinline__ uint32_t pack_h2(float lo, float hi) {
    __half2 h = __floats2half2_rn(lo, hi);
    uint32_t u; __builtin_memcpy(&u, &h, 4); return u;
}
__device__ __forceinline__ void hmma(float d[4],
    uint32_t a0, uint32_t a1, uint32_t a2, uint32_t a3,
    uint32_t b0, uint32_t b1) {
    asm volatile(
        "mma.sync.aligned.m16n8k16.row.col.f32.f16.f16.f32 "
        "{%0,%1,%2,%3}, {%4,%5,%6,%7}, {%8,%9}, {%0,%1,%2,%3};\n"
        : "+f"(d[0]), "+f"(d[1]), "+f"(d[2]), "+f"(d[3])
        : "r"(a0), "r"(a1), "r"(a2), "r"(a3), "r"(b0), "r"(b1));
}
#define LDSM_X4(r0,r1,r2,r3,a) asm volatile( \
    "ldmatrix.sync.aligned.m8n8.x4.shared.b16 {%0,%1,%2,%3}, [%4];" \
    : "=r"(r0),"=r"(r1),"=r"(r2),"=r"(r3) : "r"(a))
#define LDSM_X4T(r0,r1,r2,r3,a) asm volatile( \
    "ldmatrix.sync.aligned.m8n8.x4.trans.shared.b16 {%0,%1,%2,%3}, [%4];" \
    : "=r"(r0),"=r"(r1),"=r"(r2),"=r"(r3) : "r"(a))
__device__ __forceinline__ void cpa16(uint32_t dst, const void* src) {
    asm volatile("cp.async.cg.shared.global [%0], [%1], 16;"
                 :: "r"(dst), "l"(src) : "memory");
}
#define CPA_COMMIT() asm volatile("cp.async.commit_group;" ::: "memory")
#define CPA_WAIT0()  asm volatile("cp.async.wait_group 0;" ::: "memory")

// ---------------- prep: half copy + row stats ----------------
__global__ void prep_kernel(const float* __restrict__ q, const float* __restrict__ cp) {
    int row  = blockIdx.x * 8 + (threadIdx.x >> 5);
    int lane = threadIdx.x & 31;
    const float4* qr = (const float4*)(q + (size_t)row * DDIM);
    float4 A = qr[lane * 2], B = qr[lane * 2 + 1];
    __half h[8];
    h[0]=__float2half_rn(A.x); h[1]=__float2half_rn(A.y);
    h[2]=__float2half_rn(A.z); h[3]=__float2half_rn(A.w);
    h[4]=__float2half_rn(B.x); h[5]=__float2half_rn(B.y);
    h[6]=__float2half_rn(B.z); h[7]=__float2half_rn(B.w);
    float s = 0.0f;
#pragma unroll
    for (int i = 0; i < 8; i++) { float r = __half2float(h[i]); s += r * r; }
    uint32_t* wr = (uint32_t*)(g_qh + (size_t)row * DDIM + lane * 8);
#pragma unroll
    for (int i = 0; i < 4; i++) {
        __half2 p = __halves2half2(h[2*i], h[2*i+1]);
        uint32_t u; __builtin_memcpy(&u, &p, 4); wr[i] = u;
    }
#pragma unroll
    for (int o = 16; o > 0; o >>= 1) s += __shfl_xor_sync(0xffffffffu, s, o);
    if (lane == 0) {
        float cc = fmaxf(*cp, EPSF);
        g_qt[row] = make_float2(s, 1.0f / fmaxf(1.0f - cc * s, EPSF));
    }
}

__device__ __forceinline__ float pcalc(float s, float qni, float coef,
                                       float qnj, float kf) {
    float diff = fmaxf(qni + qnj - 2.0f * s, 0.0f);
    float arg  = fmaf(coef, diff, 1.0f);
    arg = fmaxf(arg, 1.0f + EPSF) + EPSF;
    float x = arg - 1.0f;
    float y = arg + sqrtf(x * (arg + 1.0f));
    return fex2(-kf * flg2(y));
}

__device__ __forceinline__ void prefetch_tile(uint32_t su, int tid, int kb, int b) {
    // K tile: 64 rows x 32 chunks (16B)
#pragma unroll
    for (int i = 0; i < 8; i++) {
        int f = tid + i * NTHREADS;
        int r = f >> 5, c = f & 31;
        cpa16(su + (KOFF(b) + r * KW + c * 4) * 4,
              g_qh + ((size_t)(kb + r) << 8) + c * 8);
    }
    if (tid < 32)
        cpa16(su + (STOFF(b) + tid * 4) * 4, (const float*)(g_qt + kb) + tid * 4);
    CPA_COMMIT();
}

// ---------------- main kernel ----------------
__global__ void __launch_bounds__(NTHREADS, 1)
hyp_fa_kernel(const float* __restrict__ cp) {
    extern __shared__ uint32_t sw[];
    uint32_t su;
    asm("{ .reg .u64 t; cvta.to.shared.u64 t, %1; cvt.u32.u64 %0, t; }"
        : "=r"(su) : "l"(sw));

    const int tid  = threadIdx.x;
    const int w    = tid >> 5;            // warp owns rows [16w, 16w+16)
    const int lane = tid & 31;
    const int g    = lane >> 2;
    const int tg   = lane & 3;
    const int bid  = blockIdx.x;
    const int qb   = bid >> 1;
    const int keybase = (bid & 1) * (NROWS / 2);
    const int wbase = w * 16;

    const float ccv = fmaxf(*cp, EPSF);
    const float kf  = 1.0f / sqrtf(ccv);

    // ldmatrix per-lane base offsets (bytes)
    // GEMM1 A on Q: m(i>>3): m0/m2 rows +0, m1/m3 rows +8; m0,m1 chunk c, m2,m3 chunk c+1
    const uint32_t qlb = su
        + (uint32_t)(wbase + (lane & 7) + 8 * ((lane >> 3) & 1)) * KROWB
        + (uint32_t)(lane >> 4) * 16;                        // + ks*32 per step
    // GEMM1 B on K: m0,m1 rows 8nb (chunk 2ks,2ks+1); m2,m3 rows 8nb+8
    const uint32_t k1off =
        (uint32_t)((lane & 7) + 8 * (lane >> 4)) * KROWB
        + (uint32_t)((lane >> 3) & 1) * 16;                  // + nbp*(16*528) + ks*32
    // GEMM2 B (trans) on K: m0 rows+0, m1 rows+8 (chunk nb2); m2,m3 chunk nb2+1
    const uint32_t k2off =
        (uint32_t)((lane & 7) + 8 * ((lane >> 3) & 1)) * KROWB
        + (uint32_t)(lane >> 4) * 16;                        // + ks2*(16*528) + nb2p*32

    // ---- prologue: Q tile + first K tile ----
#pragma unroll
    for (int i = 0; i < 16; i++) {
        int f = tid + i * NTHREADS;
        int r = f >> 5, c = f & 31;
        cpa16(su + (QOFF + r * QW + c * 4) * 4,
              g_qh + ((size_t)(qb * BM + r) << 8) + c * 8);
    }
    prefetch_tile(su, tid, keybase, 0);
    CPA_WAIT0();
    __syncthreads();

    const int gr0 = qb * BM + wbase + g;
    const int gr1 = gr0 + 8;
    const float2 qt0 = g_qt[gr0], qt1 = g_qt[gr1];
    const float qni0 = qt0.x, qni1 = qt1.x;
    const float tc0 = 2.0f * ccv * qt0.y;
    const float tc1 = 2.0f * ccv * qt1.y;

    float of[32][4];
#pragma unroll
    for (int n = 0; n < 32; n++)
#pragma unroll
        for (int e = 0; e < 4; e++) of[n][e] = 0.0f;
    float rsum0 = 0.0f, rsum1 = 0.0f;

    for (int jt = 0; jt < NIT; jt++) {
        const int b = jt & 1;
        CPA_WAIT0();
        __syncthreads();                       // buf b ready; prev reads done
        if (jt + 1 < NIT)
            prefetch_tile(su, tid, keybase + (jt + 1) * BN, b ^ 1);

        const uint32_t kbase = su + (uint32_t)KOFF(b) * 4;

        // ---- GEMM1: S(16x64) = Q . K^T ----
        float sf[8][4];
#pragma unroll
        for (int n = 0; n < 8; n++)
#pragma unroll
            for (int e = 0; e < 4; e++) sf[n][e] = 0.0f;
#pragma unroll
        for (int ks = 0; ks < 16; ks++) {
            uint32_t a0, a1, a2, a3;
            LDSM_X4(a0, a1, a2, a3, qlb + ks * 32);
#pragma unroll
            for (int nbp = 0; nbp < 4; nbp++) {
                uint32_t b0, b1, b2, b3;
                LDSM_X4(b0, b1, b2, b3,
                        kbase + k1off + nbp * (16 * KROWB) + ks * 32);
                hmma(sf[2 * nbp],     a0, a1, a2, a3, b0, b1);
                hmma(sf[2 * nbp + 1], a0, a1, a2, a3, b2, b3);
            }
        }

        // ---- transform: p = exp(-dist); P stays in registers (fp16) ----
        const float* st = (const float*)(sw + STOFF(b));
        const int j0 = keybase + jt * BN;
        uint32_t ph0[8], ph1[8];
#pragma unroll
        for (int nb = 0; nb < 8; nb++) {
            const int c0i = nb * 8 + 2 * tg;
            float4 qq = *(const float4*)(st + c0i * 2);   // (qn,ti, qn,ti)
            float p00 = pcalc(sf[nb][0], qni0, tc0 * qq.y, qq.x, kf);
            float p01 = pcalc(sf[nb][1], qni0, tc0 * qq.w, qq.z, kf);
            float p10 = pcalc(sf[nb][2], qni1, tc1 * qq.y, qq.x, kf);
            float p11 = pcalc(sf[nb][3], qni1, tc1 * qq.w, qq.z, kf);
            if (j0 + c0i     == gr0) p00 = 1.0f;          // exact diagonal
            if (j0 + c0i + 1 == gr0) p01 = 1.0f;
            if (j0 + c0i     == gr1) p10 = 1.0f;
            if (j0 + c0i + 1 == gr1) p11 = 1.0f;
            rsum0 += p00 + p01;
            rsum1 += p10 + p11;
            ph0[nb] = pack_h2(p00, p01);
            ph1[nb] = pack_h2(p10, p11);
        }

        // ---- GEMM2: O(16x256) += P . V ; B via ldmatrix.trans on the K tile ----
#pragma unroll
        for (int ks2 = 0; ks2 < 4; ks2++) {
            uint32_t a0 = ph0[2 * ks2],     a1 = ph1[2 * ks2];
            uint32_t a2 = ph0[2 * ks2 + 1], a3 = ph1[2 * ks2 + 1];
#pragma unroll
            for (int np = 0; np < 16; np++) {
                uint32_t b0, b1, b2, b3;
                LDSM_X4T(b0, b1, b2, b3,
                         kbase + k2off + ks2 * (16 * KROWB) + np * 32);
                hmma(of[2 * np],     a0, a1, a2, a3, b0, b1);
                hmma(of[2 * np + 1], a0, a1, a2, a3, b2, b3);
            }
        }
    }

    // ---- reduce row sums over tg ----
    rsum0 += __shfl_xor_sync(0xffffffffu, rsum0, 1);
    rsum0 += __shfl_xor_sync(0xffffffffu, rsum0, 2);
    rsum1 += __shfl_xor_sync(0xffffffffu, rsum1, 1);
    rsum1 += __shfl_xor_sync(0xffffffffu, rsum1, 2);

    // ---- epilogue: write O and l partials ----
    float* op0 = g_opart + ((size_t)bid << 15) + (size_t)(wbase + g) * DDIM;
    float* op1 = op0 + 8 * DDIM;
#pragma unroll
    for (int n = 0; n < 32; n++) {
        const int col = n * 8 + 2 * tg;
        *(float2*)(op0 + col) = make_float2(of[n][0], of[n][1]);
        *(float2*)(op1 + col) = make_float2(of[n][2], of[n][3]);
    }
    if (tg == 0) {
        g_lpart[bid * BM + wbase + g]     = rsum0;
        g_lpart[bid * BM + wbase + g + 8] = rsum1;
    }
}

// ---------------- combine: out = (O0+O1)/(l0+l1) ----------------
__global__ void combine_kernel(float* __restrict__ out) {
    int idx = blockIdx.x * 256 + threadIdx.x;     // over 524288 float4s
    int r  = idx >> 6, c4 = idx & 63;
    int qb = r >> 7, lr = r & 127;
    float l = g_lpart[(2*qb) * BM + lr] + g_lpart[(2*qb + 1) * BM + lr];
    float inv = 1.0f / l;
    const float4* o0 = (const float4*)(g_opart + ((size_t)(2*qb)     << 15) + ((size_t)lr << 8));
    const float4* o1 = (const float4*)(g_opart + ((size_t)(2*qb + 1) << 15) + ((size_t)lr << 8));
    float4 a = o0[c4], b = o1[c4];
    ((float4*)out)[idx] = make_float4((a.x + b.x) * inv, (a.y + b.y) * inv,
                                      (a.z + b.z) * inv, (a.w + b.w) * inv);
}

extern "C" void kernel_launch(void* const* d_in, const int* in_sizes, int n_in,
                              void* d_out, int out_size) {
    const float* q  = (const float*)d_in[0];
    const float* cp = (const float*)d_in[1];
    float* out      = (float*)d_out;

    cudaFuncSetAttribute(hyp_fa_kernel,
                         cudaFuncAttributeMaxDynamicSharedMemorySize, SMEM_TOTAL);

    prep_kernel<<<NROWS / 8, 256>>>(q, cp);
    hyp_fa_kernel<<<128, NTHREADS, SMEM_TOTAL>>>(cp);
    combine_kernel<<<2048, 256>>>(out);
}

// round 13
// speedup vs baseline: 2.0630x; 1.0889x over previous
#include <cuda_runtime.h>
#include <cuda_fp16.h>
#include <cstdint>

#define NROWS 8192
#define DDIM  256
#define BM    128
#define BN    64
#define NIT   64              // 4096 keys per CTA / 64
#define EPSF  1e-6f
#define NTHREADS 288          // 8 compute warps + 1 loader warp

// shared-memory layout in 32-bit WORDS
#define QW 132                // row stride (words): 132 % 32 == 4 -> conflict-free
#define KW 132
#define QOFF     0
#define KOFF(b)  (16896 + 8448*(b))    // three 64x132 K buffers
#define STOFF(b) (42240 + 128*(b))     // 64 float2 stats per buffer
#define MBARB    170496                // byte offset of mbarrier block
#define SMEM_TOTAL 170560

#define KROWB 528                      // row stride in bytes

#define MB_FULL(b) (MBARB + 16*(b))
#define MB_FREE(b) (MBARB + 16*(b) + 8)

__device__ __half g_qh[(size_t)NROWS*DDIM];    // half copy, row-major
__device__ float2 g_qt[NROWS];                 // (||q||^2, 1/t)
__device__ float  g_opart[(size_t)128*BM*DDIM];
__device__ float  g_lpart[128*BM];

__device__ __forceinline__ float flg2(float x) {
    float r; asm("lg2.approx.f32 %0, %1;" : "=f"(r) : "f"(x)); return r;
}
__device__ __forceinline__ float fex2(float x) {
    float r; asm("ex2.approx.f32 %0, %1;" : "=f"(r) : "f"(x)); return r;
}
__device__ __forceinline__ float fsqrt_ap(float x) {
    float r; asm("sqrt.approx.f32 %0, %1;" : "=f"(r) : "f"(x)); return r;
}
__device__ __forceinline__ uint32_t pack_h2(float lo, float hi) {
    __half2 h = __floats2half2_rn(lo, hi);
    uint32_t u; __builtin_memcpy(&u, &h, 4); return u;
}
__device__ __forceinline__ void hmma(float d[4],
    uint32_t a0, uint32_t a1, uint32_t a2, uint32_t a3,
    uint32_t b0, uint32_t b1) {
    asm volatile(
        "mma.sync.aligned.m16n8k16.row.col.f32.f16.f16.f32 "
        "{%0,%1,%2,%3}, {%4,%5,%6,%7}, {%8,%9}, {%0,%1,%2,%3};\n"
        : "+f"(d[0]), "+f"(d[1]), "+f"(d[2]), "+f"(d[3])
        : "r"(a0), "r"(a1), "r"(a2), "r"(a3), "r"(b0), "r"(b1));
}
#define LDSM_X4(r0,r1,r2,r3,a) asm volatile( \
    "ldmatrix.sync.aligned.m8n8.x4.shared.b16 {%0,%1,%2,%3}, [%4];" \
    : "=r"(r0),"=r"(r1),"=r"(r2),"=r"(r3) : "r"(a))
#define LDSM_X4T(r0,r1,r2,r3,a) asm volatile( \
    "ldmatrix.sync.aligned.m8n8.x4.trans.shared.b16 {%0,%1,%2,%3}, [%4];" \
    : "=r"(r0),"=r"(r1),"=r"(r2),"=r"(r3) : "r"(a))
__device__ __forceinline__ void cpa16(uint32_t dst, const void* src) {
    asm volatile("cp.async.cg.shared.global [%0], [%1], 16;"
                 :: "r"(dst), "l"(src) : "memory");
}
#define CPA_COMMIT() asm volatile("cp.async.commit_group;" ::: "memory")
#define CPA_WAIT0()  asm volatile("cp.async.wait_group 0;" ::: "memory")
#define CPA_WAIT1()  asm volatile("cp.async.wait_group 1;" ::: "memory")
#define FENCE_PROXY() asm volatile("fence.proxy.async.shared::cta;" ::: "memory")

__device__ __forceinline__ void mbar_init(uint32_t a, uint32_t c) {
    asm volatile("mbarrier.init.shared.b64 [%0], %1;" :: "r"(a), "r"(c) : "memory");
}
__device__ __forceinline__ void mbar_arrive(uint32_t a) {
    asm volatile("mbarrier.arrive.shared.b64 _, [%0];" :: "r"(a) : "memory");
}
__device__ __forceinline__ void mbar_wait(uint32_t a, uint32_t ph) {
    asm volatile(
        "{\n\t.reg .pred P1;\n\t"
        "W%=:\n\t"
        "mbarrier.try_wait.parity.acquire.cta.shared::cta.b64 P1, [%0], %1, 0x989680;\n\t"
        "@P1 bra.uni D%=;\n\t"
        "bra.uni W%=;\n\t"
        "D%=:\n\t}"
        :: "r"(a), "r"(ph) : "memory");
}

// ---------------- prep: half copy + row stats ----------------
__global__ void prep_kernel(const float* __restrict__ q, const float* __restrict__ cp) {
    int row  = blockIdx.x * 8 + (threadIdx.x >> 5);
    int lane = threadIdx.x & 31;
    const float4* qr = (const float4*)(q + (size_t)row * DDIM);
    float4 A = qr[lane * 2], B = qr[lane * 2 + 1];
    __half h[8];
    h[0]=__float2half_rn(A.x); h[1]=__float2half_rn(A.y);
    h[2]=__float2half_rn(A.z); h[3]=__float2half_rn(A.w);
    h[4]=__float2half_rn(B.x); h[5]=__float2half_rn(B.y);
    h[6]=__float2half_rn(B.z); h[7]=__float2half_rn(B.w);
    float s = 0.0f;
#pragma unroll
    for (int i = 0; i < 8; i++) { float r = __half2float(h[i]); s += r * r; }
    uint32_t* wr = (uint32_t*)(g_qh + (size_t)row * DDIM + lane * 8);
#pragma unroll
    for (int i = 0; i < 4; i++) {
        __half2 p = __halves2half2(h[2*i], h[2*i+1]);
        uint32_t u; __builtin_memcpy(&u, &p, 4); wr[i] = u;
    }
#pragma unroll
    for (int o = 16; o > 0; o >>= 1) s += __shfl_xor_sync(0xffffffffu, s, o);
    if (lane == 0) {
        float cc = fmaxf(*cp, EPSF);
        g_qt[row] = make_float2(s, 1.0f / fmaxf(1.0f - cc * s, EPSF));
    }
}

__device__ __forceinline__ float pcalc(float s, float qni, float coef,
                                       float qnj, float kf) {
    float diff = fmaxf(qni + qnj - 2.0f * s, 0.0f);
    float arg  = fmaf(coef, diff, 1.0f);
    arg = fmaxf(arg, 1.0f + EPSF) + EPSF;
    float x = arg - 1.0f;
    float y = arg + fsqrt_ap(x * (arg + 1.0f));
    return fex2(-kf * flg2(y));
}

// ---------------- main kernel: warp-specialized async pipeline ----------------
__global__ void __launch_bounds__(NTHREADS, 1)
hyp_fa_kernel(const float* __restrict__ cp) {
    extern __shared__ uint32_t sw[];
    uint32_t su;
    asm("{ .reg .u64 t; cvta.to.shared.u64 t, %1; cvt.u32.u64 %0, t; }"
        : "=r"(su) : "l"(sw));

    const int tid  = threadIdx.x;
    const int w    = tid >> 5;            // 0..7 compute, 8 loader
    const int lane = tid & 31;
    const int g    = lane >> 2;
    const int tg   = lane & 3;
    const int bid  = blockIdx.x;
    const int qb   = bid >> 1;
    const int keybase = (bid & 1) * (NROWS / 2);
    const int wbase = w * 16;

    const float ccv = fmaxf(*cp, EPSF);
    const float kf  = 1.0f / sqrtf(ccv);

    if (tid == 0) {
#pragma unroll
        for (int b = 0; b < 3; b++) {
            mbar_init(su + MB_FULL(b), 1);
            mbar_init(su + MB_FREE(b), 8);
        }
    }
    __syncthreads();   // S1: barriers visible

    // Q tile load by compute warps (their own cp.async groups)
    if (w < 8) {
#pragma unroll
        for (int i = 0; i < 16; i++) {
            int f = tid + i * 256;
            int r = f >> 5, c = f & 31;
            cpa16(su + (QOFF + r * QW + c * 4) * 4,
                  g_qh + ((size_t)(qb * BM + r) << 8) + c * 8);
        }
        CPA_COMMIT(); CPA_WAIT0();
    }
    __syncthreads();   // S2: Q visible

    // ================= loader warp =================
    if (w == 8) {
        int pph = 1, pst = 0, prev = 0;
        for (int jt = 0; jt < NIT; jt++) {
            mbar_wait(su + MB_FREE(pst), pph);
            const int kb = keybase + jt * BN;
            const uint32_t kdst = su + (uint32_t)KOFF(pst) * 4;
#pragma unroll
            for (int i = 0; i < 64; i++) {
                int f = i * 32 + lane;
                int r = f >> 5, c = f & 31;
                cpa16(kdst + (uint32_t)(r * KW + c * 4) * 4,
                      g_qh + ((size_t)(kb + r) << 8) + c * 8);
            }
            cpa16(su + (uint32_t)(STOFF(pst) + lane * 4) * 4,
                  (const float*)(g_qt + kb) + lane * 4);
            CPA_COMMIT();
            if (jt > 0) {
                CPA_WAIT1();
                FENCE_PROXY();
                if (lane == 0) mbar_arrive(su + MB_FULL(prev));
            }
            prev = pst;
            if (++pst == 3) { pst = 0; pph ^= 1; }
        }
        CPA_WAIT0();
        FENCE_PROXY();
        if (lane == 0) mbar_arrive(su + MB_FULL(prev));
        return;
    }

    // ================= compute warps =================
    // ldmatrix per-lane base offsets (bytes)
    const uint32_t qlb = su
        + (uint32_t)(wbase + (lane & 7) + 8 * ((lane >> 3) & 1)) * KROWB
        + (uint32_t)(lane >> 4) * 16;
    const uint32_t k1off =
        (uint32_t)((lane & 7) + 8 * (lane >> 4)) * KROWB
        + (uint32_t)((lane >> 3) & 1) * 16;
    const uint32_t k2off =
        (uint32_t)((lane & 7) + 8 * ((lane >> 3) & 1)) * KROWB
        + (uint32_t)(lane >> 4) * 16;

    const int gr0 = qb * BM + wbase + g;
    const int gr1 = gr0 + 8;
    const float2 qt0 = g_qt[gr0], qt1 = g_qt[gr1];
    const float qni0 = qt0.x, qni1 = qt1.x;
    const float tc0 = 2.0f * ccv * qt0.y;
    const float tc1 = 2.0f * ccv * qt1.y;

    float of[32][4];
#pragma unroll
    for (int n = 0; n < 32; n++)
#pragma unroll
        for (int e = 0; e < 4; e++) of[n][e] = 0.0f;
    float rsum0 = 0.0f, rsum1 = 0.0f;

    int cph = 0, cst = 0;
    for (int jt = 0; jt < NIT; jt++) {
        mbar_wait(su + MB_FULL(cst), cph);

        const uint32_t kbase = su + (uint32_t)KOFF(cst) * 4;

        // ---- GEMM1: S(16x64) = Q . K^T ----
        float sf[8][4];
#pragma unroll
        for (int n = 0; n < 8; n++)
#pragma unroll
            for (int e = 0; e < 4; e++) sf[n][e] = 0.0f;
#pragma unroll
        for (int ks = 0; ks < 16; ks++) {
            uint32_t a0, a1, a2, a3;
            LDSM_X4(a0, a1, a2, a3, qlb + ks * 32);
#pragma unroll
            for (int nbp = 0; nbp < 4; nbp++) {
                uint32_t b0, b1, b2, b3;
                LDSM_X4(b0, b1, b2, b3,
                        kbase + k1off + nbp * (16 * KROWB) + ks * 32);
                hmma(sf[2 * nbp],     a0, a1, a2, a3, b0, b1);
                hmma(sf[2 * nbp + 1], a0, a1, a2, a3, b2, b3);
            }
        }

        // ---- transform: p = exp(-dist); P stays in registers ----
        const float* st = (const float*)(sw + STOFF(cst));
        const int j0 = keybase + jt * BN;
        uint32_t ph0[8], ph1[8];
#pragma unroll
        for (int nb = 0; nb < 8; nb++) {
            const int c0i = nb * 8 + 2 * tg;
            float4 qq = *(const float4*)(st + c0i * 2);
            float p00 = pcalc(sf[nb][0], qni0, tc0 * qq.y, qq.x, kf);
            float p01 = pcalc(sf[nb][1], qni0, tc0 * qq.w, qq.z, kf);
            float p10 = pcalc(sf[nb][2], qni1, tc1 * qq.y, qq.x, kf);
            float p11 = pcalc(sf[nb][3], qni1, tc1 * qq.w, qq.z, kf);
            if (j0 + c0i     == gr0) p00 = 1.0f;
            if (j0 + c0i + 1 == gr0) p01 = 1.0f;
            if (j0 + c0i     == gr1) p10 = 1.0f;
            if (j0 + c0i + 1 == gr1) p11 = 1.0f;
            rsum0 += p00 + p01;
            rsum1 += p10 + p11;
            ph0[nb] = pack_h2(p00, p01);
            ph1[nb] = pack_h2(p10, p11);
        }

        // ---- GEMM2: O(16x256) += P . V (B via ldmatrix.trans on K tile) ----
#pragma unroll
        for (int ks2 = 0; ks2 < 4; ks2++) {
            uint32_t a0 = ph0[2 * ks2],     a1 = ph1[2 * ks2];
            uint32_t a2 = ph0[2 * ks2 + 1], a3 = ph1[2 * ks2 + 1];
#pragma unroll
            for (int np = 0; np < 16; np++) {
                uint32_t b0, b1, b2, b3;
                LDSM_X4T(b0, b1, b2, b3,
                         kbase + k2off + ks2 * (16 * KROWB) + np * 32);
                hmma(of[2 * np],     a0, a1, a2, a3, b0, b1);
                hmma(of[2 * np + 1], a0, a1, a2, a3, b2, b3);
            }
        }

        __syncwarp();
        if (lane == 0) mbar_arrive(su + MB_FREE(cst));
        if (++cst == 3) { cst = 0; cph ^= 1; }
    }

    // ---- reduce row sums over tg ----
    rsum0 += __shfl_xor_sync(0xffffffffu, rsum0, 1);
    rsum0 += __shfl_xor_sync(0xffffffffu, rsum0, 2);
    rsum1 += __shfl_xor_sync(0xffffffffu, rsum1, 1);
    rsum1 += __shfl_xor_sync(0xffffffffu, rsum1, 2);

    // ---- epilogue: write O and l partials ----
    float* op0 = g_opart + ((size_t)bid << 15) + (size_t)(wbase + g) * DDIM;
    float* op1 = op0 + 8 * DDIM;
#pragma unroll
    for (int n = 0; n < 32; n++) {
        const int col = n * 8 + 2 * tg;
        *(float2*)(op0 + col) = make_float2(of[n][0], of[n][1]);
        *(float2*)(op1 + col) = make_float2(of[n][2], of[n][3]);
    }
    if (tg == 0) {
        g_lpart[bid * BM + wbase + g]     = rsum0;
        g_lpart[bid * BM + wbase + g + 8] = rsum1;
    }
}

// ---------------- combine: out = (O0+O1)/(l0+l1) ----------------
__global__ void combine_kernel(float* __restrict__ out) {
    int idx = blockIdx.x * 256 + threadIdx.x;     // over 524288 float4s
    int r  = idx >> 6, c4 = idx & 63;
    int qb = r >> 7, lr = r & 127;
    float l = g_lpart[(2*qb) * BM + lr] + g_lpart[(2*qb + 1) * BM + lr];
    float inv = 1.0f / l;
    const float4* o0 = (const float4*)(g_opart + ((size_t)(2*qb)     << 15) + ((size_t)lr << 8));
    const float4* o1 = (const float4*)(g_opart + ((size_t)(2*qb + 1) << 15) + ((size_t)lr << 8));
    float4 a = o0[c4], b = o1[c4];
    ((float4*)out)[idx] = make_float4((a.x + b.x) * inv, (a.y + b.y) * inv,
                                      (a.z + b.z) * inv, (a.w + b.w) * inv);
}

extern "C" void kernel_launch(void* const* d_in, const int* in_sizes, int n_in,
                              void* d_out, int out_size) {
    const float* q  = (const float*)d_in[0];
    const float* cp = (const float*)d_in[1];
    float* out      = (float*)d_out;

    cudaFuncSetAttribute(hyp_fa_kernel,
                         cudaFuncAttributeMaxDynamicSharedMemorySize, SMEM_TOTAL);

    prep_kernel<<<NROWS / 8, 256>>>(q, cp);
    hyp_fa_kernel<<<128, NTHREADS, SMEM_TOTAL>>>(cp);
    combine_kernel<<<2048, 256>>>(out);
}

// round 14
// speedup vs baseline: 2.0886x; 1.0124x over previous
#include <cuda_runtime.h>
#include <cuda_fp16.h>
#include <cstdint>

#define NROWS 8192
#define DDIM  256
#define BM    128
#define BN    64
#define NIT   64              // 4096 keys per CTA / 64
#define EPSF  1e-6f
#define NTHREADS 288          // 8 compute warps + 1 loader warp

// shared-memory layout in 32-bit WORDS
#define QW 132                // row stride (words): 132 % 32 == 4 -> conflict-free
#define KW 132
#define QOFF     0
#define KOFF(b)  (16896 + 8448*(b))    // three 64x132 K buffers
#define STOFF(b) (42240 + 128*(b))     // 64 float2 stats per buffer
#define MBARB    170496                // byte offset of mbarrier block
#define SMEM_TOTAL 170560

#define KROWB 528                      // row stride in bytes

#define MB_FULL(b) (MBARB + 16*(b))
#define MB_FREE(b) (MBARB + 16*(b) + 8)

__device__ __half g_qh[(size_t)NROWS*DDIM];    // half copy, row-major
__device__ float2 g_qt[NROWS];                 // (||q||^2, 1/t)
__device__ float  g_opart[(size_t)128*BM*DDIM];
__device__ float  g_lpart[128*BM];

__device__ __forceinline__ float flg2(float x) {
    float r; asm("lg2.approx.f32 %0, %1;" : "=f"(r) : "f"(x)); return r;
}
__device__ __forceinline__ float fex2(float x) {
    float r; asm("ex2.approx.f32 %0, %1;" : "=f"(r) : "f"(x)); return r;
}
__device__ __forceinline__ float fsqrt_ap(float x) {
    float r; asm("sqrt.approx.f32 %0, %1;" : "=f"(r) : "f"(x)); return r;
}
__device__ __forceinline__ uint32_t pack_h2(float lo, float hi) {
    __half2 h = __floats2half2_rn(lo, hi);
    uint32_t u; __builtin_memcpy(&u, &h, 4); return u;
}
// f32-accumulator HMMA (GEMM2)
__device__ __forceinline__ void hmma(float d[4],
    uint32_t a0, uint32_t a1, uint32_t a2, uint32_t a3,
    uint32_t b0, uint32_t b1) {
    asm volatile(
        "mma.sync.aligned.m16n8k16.row.col.f32.f16.f16.f32 "
        "{%0,%1,%2,%3}, {%4,%5,%6,%7}, {%8,%9}, {%0,%1,%2,%3};\n"
        : "+f"(d[0]), "+f"(d[1]), "+f"(d[2]), "+f"(d[3])
        : "r"(a0), "r"(a1), "r"(a2), "r"(a3), "r"(b0), "r"(b1));
}
// f16-accumulator HMMA (GEMM1) - double rate on legacy tensor path
__device__ __forceinline__ void hmma16(uint32_t d[2],
    uint32_t a0, uint32_t a1, uint32_t a2, uint32_t a3,
    uint32_t b0, uint32_t b1) {
    asm volatile(
        "mma.sync.aligned.m16n8k16.row.col.f16.f16.f16.f16 "
        "{%0,%1}, {%2,%3,%4,%5}, {%6,%7}, {%0,%1};\n"
        : "+r"(d[0]), "+r"(d[1])
        : "r"(a0), "r"(a1), "r"(a2), "r"(a3), "r"(b0), "r"(b1));
}
#define LDSM_X4(r0,r1,r2,r3,a) asm volatile( \
    "ldmatrix.sync.aligned.m8n8.x4.shared.b16 {%0,%1,%2,%3}, [%4];" \
    : "=r"(r0),"=r"(r1),"=r"(r2),"=r"(r3) : "r"(a))
#define LDSM_X4T(r0,r1,r2,r3,a) asm volatile( \
    "ldmatrix.sync.aligned.m8n8.x4.trans.shared.b16 {%0,%1,%2,%3}, [%4];" \
    : "=r"(r0),"=r"(r1),"=r"(r2),"=r"(r3) : "r"(a))
__device__ __forceinline__ void cpa16(uint32_t dst, const void* src) {
    asm volatile("cp.async.cg.shared.global [%0], [%1], 16;"
                 :: "r"(dst), "l"(src) : "memory");
}
#define CPA_COMMIT() asm volatile("cp.async.commit_group;" ::: "memory")
#define CPA_WAIT0()  asm volatile("cp.async.wait_group 0;" ::: "memory")
#define CPA_WAIT1()  asm volatile("cp.async.wait_group 1;" ::: "memory")
#define FENCE_PROXY() asm volatile("fence.proxy.async.shared::cta;" ::: "memory")

__device__ __forceinline__ void mbar_init(uint32_t a, uint32_t c) {
    asm volatile("mbarrier.init.shared.b64 [%0], %1;" :: "r"(a), "r"(c) : "memory");
}
__device__ __forceinline__ void mbar_arrive(uint32_t a) {
    asm volatile("mbarrier.arrive.shared.b64 _, [%0];" :: "r"(a) : "memory");
}
__device__ __forceinline__ void mbar_wait(uint32_t a, uint32_t ph) {
    asm volatile(
        "{\n\t.reg .pred P1;\n\t"
        "W%=:\n\t"
        "mbarrier.try_wait.parity.acquire.cta.shared::cta.b64 P1, [%0], %1, 0x989680;\n\t"
        "@P1 bra.uni D%=;\n\t"
        "bra.uni W%=;\n\t"
        "D%=:\n\t}"
        :: "r"(a), "r"(ph) : "memory");
}

// ---------------- prep: half copy + row stats ----------------
__global__ void prep_kernel(const float* __restrict__ q, const float* __restrict__ cp) {
    int row  = blockIdx.x * 8 + (threadIdx.x >> 5);
    int lane = threadIdx.x & 31;
    const float4* qr = (const float4*)(q + (size_t)row * DDIM);
    float4 A = qr[lane * 2], B = qr[lane * 2 + 1];
    __half h[8];
    h[0]=__float2half_rn(A.x); h[1]=__float2half_rn(A.y);
    h[2]=__float2half_rn(A.z); h[3]=__float2half_rn(A.w);
    h[4]=__float2half_rn(B.x); h[5]=__float2half_rn(B.y);
    h[6]=__float2half_rn(B.z); h[7]=__float2half_rn(B.w);
    float s = 0.0f;
#pragma unroll
    for (int i = 0; i < 8; i++) { float r = __half2float(h[i]); s += r * r; }
    uint32_t* wr = (uint32_t*)(g_qh + (size_t)row * DDIM + lane * 8);
#pragma unroll
    for (int i = 0; i < 4; i++) {
        __half2 p = __halves2half2(h[2*i], h[2*i+1]);
        uint32_t u; __builtin_memcpy(&u, &p, 4); wr[i] = u;
    }
#pragma unroll
    for (int o = 16; o > 0; o >>= 1) s += __shfl_xor_sync(0xffffffffu, s, o);
    if (lane == 0) {
        float cc = fmaxf(*cp, EPSF);
        g_qt[row] = make_float2(s, 1.0f / fmaxf(1.0f - cc * s, EPSF));
    }
}

__device__ __forceinline__ float pcalc(float s, float qni, float coef,
                                       float qnj, float kf) {
    float diff = fmaxf(qni + qnj - 2.0f * s, 0.0f);
    float arg  = fmaf(coef, diff, 1.0f);
    arg = fmaxf(arg, 1.0f + EPSF) + EPSF;
    float x = arg - 1.0f;
    float y = arg + fsqrt_ap(x * (arg + 1.0f));
    return fex2(-kf * flg2(y));
}

// ---------------- main kernel: warp-specialized async pipeline ----------------
__global__ void __launch_bounds__(NTHREADS, 1)
hyp_fa_kernel(const float* __restrict__ cp) {
    extern __shared__ uint32_t sw[];
    uint32_t su;
    asm("{ .reg .u64 t; cvta.to.shared.u64 t, %1; cvt.u32.u64 %0, t; }"
        : "=r"(su) : "l"(sw));

    const int tid  = threadIdx.x;
    const int w    = tid >> 5;            // 0..7 compute, 8 loader
    const int lane = tid & 31;
    const int g    = lane >> 2;
    const int tg   = lane & 3;
    const int bid  = blockIdx.x;
    const int qb   = bid >> 1;
    const int keybase = (bid & 1) * (NROWS / 2);
    const int wbase = w * 16;

    const float ccv = fmaxf(*cp, EPSF);
    const float kf  = 1.0f / sqrtf(ccv);

    if (tid == 0) {
#pragma unroll
        for (int b = 0; b < 3; b++) {
            mbar_init(su + MB_FULL(b), 1);
            mbar_init(su + MB_FREE(b), 8);
        }
    }
    __syncthreads();   // S1: barriers visible

    // Q tile load by compute warps
    if (w < 8) {
#pragma unroll
        for (int i = 0; i < 16; i++) {
            int f = tid + i * 256;
            int r = f >> 5, c = f & 31;
            cpa16(su + (QOFF + r * QW + c * 4) * 4,
                  g_qh + ((size_t)(qb * BM + r) << 8) + c * 8);
        }
        CPA_COMMIT(); CPA_WAIT0();
    }
    __syncthreads();   // S2: Q visible

    // ================= loader warp =================
    if (w == 8) {
        int pph = 1, pst = 0, prev = 0;
        for (int jt = 0; jt < NIT; jt++) {
            mbar_wait(su + MB_FREE(pst), pph);
            const int kb = keybase + jt * BN;
            const uint32_t kdst = su + (uint32_t)KOFF(pst) * 4;
#pragma unroll
            for (int i = 0; i < 64; i++) {
                int f = i * 32 + lane;
                int r = f >> 5, c = f & 31;
                cpa16(kdst + (uint32_t)(r * KW + c * 4) * 4,
                      g_qh + ((size_t)(kb + r) << 8) + c * 8);
            }
            cpa16(su + (uint32_t)(STOFF(pst) + lane * 4) * 4,
                  (const float*)(g_qt + kb) + lane * 4);
            CPA_COMMIT();
            if (jt > 0) {
                CPA_WAIT1();
                FENCE_PROXY();
                if (lane == 0) mbar_arrive(su + MB_FULL(prev));
            }
            prev = pst;
            if (++pst == 3) { pst = 0; pph ^= 1; }
        }
        CPA_WAIT0();
        FENCE_PROXY();
        if (lane == 0) mbar_arrive(su + MB_FULL(prev));
        return;
    }

    // ================= compute warps =================
    const uint32_t qlb = su
        + (uint32_t)(wbase + (lane & 7) + 8 * ((lane >> 3) & 1)) * KROWB
        + (uint32_t)(lane >> 4) * 16;
    const uint32_t k1off =
        (uint32_t)((lane & 7) + 8 * (lane >> 4)) * KROWB
        + (uint32_t)((lane >> 3) & 1) * 16;
    const uint32_t k2off =
        (uint32_t)((lane & 7) + 8 * ((lane >> 3) & 1)) * KROWB
        + (uint32_t)(lane >> 4) * 16;

    const int gr0 = qb * BM + wbase + g;
    const int gr1 = gr0 + 8;
    const float2 qt0 = g_qt[gr0], qt1 = g_qt[gr1];
    const float qni0 = qt0.x, qni1 = qt1.x;
    const float tc0 = 2.0f * ccv * qt0.y;
    const float tc1 = 2.0f * ccv * qt1.y;

    float of[32][4];
#pragma unroll
    for (int n = 0; n < 32; n++)
#pragma unroll
        for (int e = 0; e < 4; e++) of[n][e] = 0.0f;
    float rsum0 = 0.0f, rsum1 = 0.0f;

    int cph = 0, cst = 0;
    for (int jt = 0; jt < NIT; jt++) {
        mbar_wait(su + MB_FULL(cst), cph);

        const uint32_t kbase = su + (uint32_t)KOFF(cst) * 4;

        // ---- GEMM1: S(16x64) = Q . K^T  (f16 accumulators) ----
        uint32_t sh[8][2];
#pragma unroll
        for (int n = 0; n < 8; n++) { sh[n][0] = 0u; sh[n][1] = 0u; }
#pragma unroll
        for (int ks = 0; ks < 16; ks++) {
            uint32_t a0, a1, a2, a3;
            LDSM_X4(a0, a1, a2, a3, qlb + ks * 32);
#pragma unroll
            for (int nbp = 0; nbp < 4; nbp++) {
                uint32_t b0, b1, b2, b3;
                LDSM_X4(b0, b1, b2, b3,
                        kbase + k1off + nbp * (16 * KROWB) + ks * 32);
                hmma16(sh[2 * nbp],     a0, a1, a2, a3, b0, b1);
                hmma16(sh[2 * nbp + 1], a0, a1, a2, a3, b2, b3);
            }
        }

        // ---- fused transform + GEMM2 (per 16-key chunk) ----
        const float* st = (const float*)(sw + STOFF(cst));
        const int j0 = keybase + jt * BN;
#pragma unroll
        for (int ks2 = 0; ks2 < 4; ks2++) {
            uint32_t pa[4];   // a0..a3 for this GEMM2 step
#pragma unroll
            for (int h = 0; h < 2; h++) {
                const int nb = 2 * ks2 + h;
                const int c0i = nb * 8 + 2 * tg;
                float4 qq = *(const float4*)(st + c0i * 2);
                __half2 h2a, h2b;
                __builtin_memcpy(&h2a, &sh[nb][0], 4);
                __builtin_memcpy(&h2b, &sh[nb][1], 4);
                float2 s01 = __half22float2(h2a);   // row g,   cols c0i,c0i+1
                float2 s23 = __half22float2(h2b);   // row g+8
                float p00 = pcalc(s01.x, qni0, tc0 * qq.y, qq.x, kf);
                float p01 = pcalc(s01.y, qni0, tc0 * qq.w, qq.z, kf);
                float p10 = pcalc(s23.x, qni1, tc1 * qq.y, qq.x, kf);
                float p11 = pcalc(s23.y, qni1, tc1 * qq.w, qq.z, kf);
                if (j0 + c0i     == gr0) p00 = 1.0f;
                if (j0 + c0i + 1 == gr0) p01 = 1.0f;
                if (j0 + c0i     == gr1) p10 = 1.0f;
                if (j0 + c0i + 1 == gr1) p11 = 1.0f;
                rsum0 += p00 + p01;
                rsum1 += p10 + p11;
                pa[h]     = pack_h2(p00, p01);
                pa[2 + h] = pack_h2(p10, p11);
            }
#pragma unroll
            for (int np = 0; np < 16; np++) {
                uint32_t b0, b1, b2, b3;
                LDSM_X4T(b0, b1, b2, b3,
                         kbase + k2off + ks2 * (16 * KROWB) + np * 32);
                hmma(of[2 * np],     pa[0], pa[2], pa[1], pa[3], b0, b1);
                hmma(of[2 * np + 1], pa[0], pa[2], pa[1], pa[3], b2, b3);
            }
        }

        __syncwarp();
        if (lane == 0) mbar_arrive(su + MB_FREE(cst));
        if (++cst == 3) { cst = 0; cph ^= 1; }
    }

    // ---- reduce row sums over tg ----
    rsum0 += __shfl_xor_sync(0xffffffffu, rsum0, 1);
    rsum0 += __shfl_xor_sync(0xffffffffu, rsum0, 2);
    rsum1 += __shfl_xor_sync(0xffffffffu, rsum1, 1);
    rsum1 += __shfl_xor_sync(0xffffffffu, rsum1, 2);

    // ---- epilogue: write O and l partials ----
    float* op0 = g_opart + ((size_t)bid << 15) + (size_t)(wbase + g) * DDIM;
    float* op1 = op0 + 8 * DDIM;
#pragma unroll
    for (int n = 0; n < 32; n++) {
        const int col = n * 8 + 2 * tg;
        *(float2*)(op0 + col) = make_float2(of[n][0], of[n][1]);
        *(float2*)(op1 + col) = make_float2(of[n][2], of[n][3]);
    }
    if (tg == 0) {
        g_lpart[bid * BM + wbase + g]     = rsum0;
        g_lpart[bid * BM + wbase + g + 8] = rsum1;
    }
}

// ---------------- combine: out = (O0+O1)/(l0+l1) ----------------
__global__ void combine_kernel(float* __restrict__ out) {
    int idx = blockIdx.x * 256 + threadIdx.x;     // over 524288 float4s
    int r  = idx >> 6, c4 = idx & 63;
    int qb = r >> 7, lr = r & 127;
    float l = g_lpart[(2*qb) * BM + lr] + g_lpart[(2*qb + 1) * BM + lr];
    float inv = 1.0f / l;
    const float4* o0 = (const float4*)(g_opart + ((size_t)(2*qb)     << 15) + ((size_t)lr << 8));
    const float4* o1 = (const float4*)(g_opart + ((size_t)(2*qb + 1) << 15) + ((size_t)lr << 8));
    float4 a = o0[c4], b = o1[c4];
    ((float4*)out)[idx] = make_float4((a.x + b.x) * inv, (a.y + b.y) * inv,
                                      (a.z + b.z) * inv, (a.w + b.w) * inv);
}

extern "C" void kernel_launch(void* const* d_in, const int* in_sizes, int n_in,
                              void* d_out, int out_size) {
    const float* q  = (const float*)d_in[0];
    const float* cp = (const float*)d_in[1];
    float* out      = (float*)d_out;

    cudaFuncSetAttribute(hyp_fa_kernel,
                         cudaFuncAttributeMaxDynamicSharedMemorySize, SMEM_TOTAL);

    prep_kernel<<<NROWS / 8, 256>>>(q, cp);
    hyp_fa_kernel<<<128, NTHREADS, SMEM_TOTAL>>>(cp);
    combine_kernel<<<2048, 256>>>(out);
}

// round 15
// speedup vs baseline: 2.3747x; 1.1370x over previous
#include <cuda_runtime.h>
#include <cuda_fp16.h>
#include <cstdint>

#define NROWS 8192
#define DDIM  256
#define BM    128
#define BN    64
#define EPSF  1e-6f
#define NTHREADS 288          // 8 compute warps + 1 loader warp
#define NCTA  148
// job partition: 8192 jobs = 52 CTAs x 56 + 96 CTAs x 55
#define JSTART(c) (55*(c) + ((c) < 52 ? (c) : 52))
#define JCNT(c)   ((c) < 52 ? 56 : 55)

// shared-memory layout in 32-bit WORDS
#define QW 132                // row stride (words): 132 % 32 == 4 -> conflict-free
#define KW 132
#define QOFF     0
#define KOFF(b)  (16896 + 8448*(b))    // three 64x132 K buffers
#define STOFF(b) (42240 + 128*(b))     // 64 float2 stats per buffer
#define MBARB    170496                // byte offset of mbarrier block
#define SMEM_TOTAL 170560

#define KROWB 528                      // row stride in bytes

#define MB_FULL(b) (MBARB + 16*(b))
#define MB_FREE(b) (MBARB + 16*(b) + 8)

__device__ __half g_qh[(size_t)NROWS*DDIM];    // half copy, row-major
__device__ float2 g_qt[NROWS];                 // (||q||^2, 1/t)
__device__ float  g_opart[(size_t)2*NCTA*BM*DDIM];   // 296 slots
__device__ float  g_lpart[2*NCTA*BM];

__device__ __forceinline__ float flg2(float x) {
    float r; asm("lg2.approx.f32 %0, %1;" : "=f"(r) : "f"(x)); return r;
}
__device__ __forceinline__ float fex2(float x) {
    float r; asm("ex2.approx.f32 %0, %1;" : "=f"(r) : "f"(x)); return r;
}
__device__ __forceinline__ float fsqrt_ap(float x) {
    float r; asm("sqrt.approx.f32 %0, %1;" : "=f"(r) : "f"(x)); return r;
}
__device__ __forceinline__ uint32_t pack_h2(float lo, float hi) {
    __half2 h = __floats2half2_rn(lo, hi);
    uint32_t u; __builtin_memcpy(&u, &h, 4); return u;
}
__device__ __forceinline__ void hmma(float d[4],
    uint32_t a0, uint32_t a1, uint32_t a2, uint32_t a3,
    uint32_t b0, uint32_t b1) {
    asm volatile(
        "mma.sync.aligned.m16n8k16.row.col.f32.f16.f16.f32 "
        "{%0,%1,%2,%3}, {%4,%5,%6,%7}, {%8,%9}, {%0,%1,%2,%3};\n"
        : "+f"(d[0]), "+f"(d[1]), "+f"(d[2]), "+f"(d[3])
        : "r"(a0), "r"(a1), "r"(a2), "r"(a3), "r"(b0), "r"(b1));
}
__device__ __forceinline__ void hmma16(uint32_t d[2],
    uint32_t a0, uint32_t a1, uint32_t a2, uint32_t a3,
    uint32_t b0, uint32_t b1) {
    asm volatile(
        "mma.sync.aligned.m16n8k16.row.col.f16.f16.f16.f16 "
        "{%0,%1}, {%2,%3,%4,%5}, {%6,%7}, {%0,%1};\n"
        : "+r"(d[0]), "+r"(d[1])
        : "r"(a0), "r"(a1), "r"(a2), "r"(a3), "r"(b0), "r"(b1));
}
#define LDSM_X4(r0,r1,r2,r3,a) asm volatile( \
    "ldmatrix.sync.aligned.m8n8.x4.shared.b16 {%0,%1,%2,%3}, [%4];" \
    : "=r"(r0),"=r"(r1),"=r"(r2),"=r"(r3) : "r"(a))
#define LDSM_X4T(r0,r1,r2,r3,a) asm volatile( \
    "ldmatrix.sync.aligned.m8n8.x4.trans.shared.b16 {%0,%1,%2,%3}, [%4];" \
    : "=r"(r0),"=r"(r1),"=r"(r2),"=r"(r3) : "r"(a))
__device__ __forceinline__ void cpa16(uint32_t dst, const void* src) {
    asm volatile("cp.async.cg.shared.global [%0], [%1], 16;"
                 :: "r"(dst), "l"(src) : "memory");
}
#define CPA_COMMIT() asm volatile("cp.async.commit_group;" ::: "memory")
#define CPA_WAIT0()  asm volatile("cp.async.wait_group 0;" ::: "memory")
#define CPA_WAIT1()  asm volatile("cp.async.wait_group 1;" ::: "memory")
#define FENCE_PROXY() asm volatile("fence.proxy.async.shared::cta;" ::: "memory")
#define CBAR() asm volatile("bar.sync 1, 256;" ::: "memory")  // 8 compute warps

__device__ __forceinline__ void mbar_init(uint32_t a, uint32_t c) {
    asm volatile("mbarrier.init.shared.b64 [%0], %1;" :: "r"(a), "r"(c) : "memory");
}
__device__ __forceinline__ void mbar_arrive(uint32_t a) {
    asm volatile("mbarrier.arrive.shared.b64 _, [%0];" :: "r"(a) : "memory");
}
__device__ __forceinline__ void mbar_wait(uint32_t a, uint32_t ph) {
    asm volatile(
        "{\n\t.reg .pred P1;\n\t"
        "W%=:\n\t"
        "mbarrier.try_wait.parity.acquire.cta.shared::cta.b64 P1, [%0], %1, 0x989680;\n\t"
        "@P1 bra.uni D%=;\n\t"
        "bra.uni W%=;\n\t"
        "D%=:\n\t}"
        :: "r"(a), "r"(ph) : "memory");
}

// ---------------- prep: half copy + row stats ----------------
__global__ void prep_kernel(const float* __restrict__ q, const float* __restrict__ cp) {
    int row  = blockIdx.x * 8 + (threadIdx.x >> 5);
    int lane = threadIdx.x & 31;
    const float4* qr = (const float4*)(q + (size_t)row * DDIM);
    float4 A = qr[lane * 2], B = qr[lane * 2 + 1];
    __half h[8];
    h[0]=__float2half_rn(A.x); h[1]=__float2half_rn(A.y);
    h[2]=__float2half_rn(A.z); h[3]=__float2half_rn(A.w);
    h[4]=__float2half_rn(B.x); h[5]=__float2half_rn(B.y);
    h[6]=__float2half_rn(B.z); h[7]=__float2half_rn(B.w);
    float s = 0.0f;
#pragma unroll
    for (int i = 0; i < 8; i++) { float r = __half2float(h[i]); s += r * r; }
    uint32_t* wr = (uint32_t*)(g_qh + (size_t)row * DDIM + lane * 8);
#pragma unroll
    for (int i = 0; i < 4; i++) {
        __half2 p = __halves2half2(h[2*i], h[2*i+1]);
        uint32_t u; __builtin_memcpy(&u, &p, 4); wr[i] = u;
    }
#pragma unroll
    for (int o = 16; o > 0; o >>= 1) s += __shfl_xor_sync(0xffffffffu, s, o);
    if (lane == 0) {
        float cc = fmaxf(*cp, EPSF);
        g_qt[row] = make_float2(s, 1.0f / fmaxf(1.0f - cc * s, EPSF));
    }
}

__device__ __forceinline__ float pcalc(float s, float qni, float coef,
                                       float qnj, float kf) {
    float diff = fmaxf(qni + qnj - 2.0f * s, 0.0f);
    float arg  = fmaf(coef, diff, 1.0f);
    arg = fmaxf(arg, 1.0f + EPSF) + EPSF;
    float x = arg - 1.0f;
    float y = arg + fsqrt_ap(x * (arg + 1.0f));
    return fex2(-kf * flg2(y));
}

// ---------------- main kernel ----------------
__global__ void __launch_bounds__(NTHREADS, 1)
hyp_fa_kernel(const float* __restrict__ cp) {
    extern __shared__ uint32_t sw[];
    uint32_t su;
    asm("{ .reg .u64 t; cvta.to.shared.u64 t, %1; cvt.u32.u64 %0, t; }"
        : "=r"(su) : "l"(sw));

    const int tid  = threadIdx.x;
    const int w    = tid >> 5;            // 0..7 compute, 8 loader
    const int lane = tid & 31;
    const int g    = lane >> 2;
    const int tg   = lane & 3;
    const int cta  = blockIdx.x;
    const int jstart = JSTART(cta);
    const int jcnt   = JCNT(cta);
    const int wbase  = w * 16;

    const float ccv = fmaxf(*cp, EPSF);
    const float kf  = 1.0f / sqrtf(ccv);

    if (tid == 0) {
#pragma unroll
        for (int b = 0; b < 3; b++) {
            mbar_init(su + MB_FULL(b), 1);
            mbar_init(su + MB_FREE(b), 8);
        }
    }
    __syncthreads();   // barriers visible

    // ================= loader warp =================
    if (w == 8) {
        int pph = 1, pst = 0, prev = 0;
        for (int jt = 0; jt < jcnt; jt++) {
            mbar_wait(su + MB_FREE(pst), pph);
            const int kb = ((jstart + jt) & 127) << 6;   // key base row
            const uint32_t kdst = su + (uint32_t)KOFF(pst) * 4;
#pragma unroll
            for (int i = 0; i < 64; i++) {
                int f = i * 32 + lane;
                int r = f >> 5, c = f & 31;
                cpa16(kdst + (uint32_t)(r * KW + c * 4) * 4,
                      g_qh + ((size_t)(kb + r) << 8) + c * 8);
            }
            cpa16(su + (uint32_t)(STOFF(pst) + lane * 4) * 4,
                  (const float*)(g_qt + kb) + lane * 4);
            CPA_COMMIT();
            if (jt > 0) {
                CPA_WAIT1();
                FENCE_PROXY();
                if (lane == 0) mbar_arrive(su + MB_FULL(prev));
            }
            prev = pst;
            if (++pst == 3) { pst = 0; pph ^= 1; }
        }
        CPA_WAIT0();
        FENCE_PROXY();
        if (lane == 0) mbar_arrive(su + MB_FULL(prev));
        return;
    }

    // ================= compute warps =================
    const uint32_t qlb = su
        + (uint32_t)(wbase + (lane & 7) + 8 * ((lane >> 3) & 1)) * KROWB
        + (uint32_t)(lane >> 4) * 16;
    const uint32_t k1off =
        (uint32_t)((lane & 7) + 8 * (lane >> 4)) * KROWB
        + (uint32_t)((lane >> 3) & 1) * 16;
    const uint32_t k2off =
        (uint32_t)((lane & 7) + 8 * ((lane >> 3) & 1)) * KROWB
        + (uint32_t)(lane >> 4) * 16;

    int cst = 0, cph = 0;
    int j = jstart;
    const int jend = jstart + jcnt;
    int seg = 0;

    while (j < jend) {
        const int Q = j >> 7;
        const int segend = (jend < ((Q + 1) << 7)) ? jend : ((Q + 1) << 7);

        // ---- (re)load Q tile for qblock Q ----
        CBAR();                               // all compute warps done with old Q
#pragma unroll
        for (int i = 0; i < 16; i++) {
            int f = tid + i * 256;
            int r = f >> 5, c = f & 31;
            cpa16(su + (QOFF + r * QW + c * 4) * 4,
                  g_qh + ((size_t)(Q * BM + r) << 8) + c * 8);
        }
        CPA_COMMIT(); CPA_WAIT0();
        CBAR();                               // new Q visible to all

        const int gr0 = (Q << 7) + wbase + g;
        const int gr1 = gr0 + 8;
        const float2 qt0 = g_qt[gr0], qt1 = g_qt[gr1];
        const float qni0 = qt0.x, qni1 = qt1.x;
        const float tc0 = 2.0f * ccv * qt0.y;
        const float tc1 = 2.0f * ccv * qt1.y;

        float of[32][4];
#pragma unroll
        for (int n = 0; n < 32; n++)
#pragma unroll
            for (int e = 0; e < 4; e++) of[n][e] = 0.0f;
        float rsum0 = 0.0f, rsum1 = 0.0f;

        for (; j < segend; j++) {
            mbar_wait(su + MB_FULL(cst), cph);
            const uint32_t kbase = su + (uint32_t)KOFF(cst) * 4;
            const int j0key = (j & 127) << 6;

            // ---- GEMM1: S(16x64) = Q . K^T  (f16 accumulators) ----
            uint32_t sh[8][2];
#pragma unroll
            for (int n = 0; n < 8; n++) { sh[n][0] = 0u; sh[n][1] = 0u; }
#pragma unroll
            for (int ks = 0; ks < 16; ks++) {
                uint32_t a0, a1, a2, a3;
                LDSM_X4(a0, a1, a2, a3, qlb + ks * 32);
#pragma unroll
                for (int nbp = 0; nbp < 4; nbp++) {
                    uint32_t b0, b1, b2, b3;
                    LDSM_X4(b0, b1, b2, b3,
                            kbase + k1off + nbp * (16 * KROWB) + ks * 32);
                    hmma16(sh[2 * nbp],     a0, a1, a2, a3, b0, b1);
                    hmma16(sh[2 * nbp + 1], a0, a1, a2, a3, b2, b3);
                }
            }

            // ---- fused transform + GEMM2 ----
            const float* st = (const float*)(sw + STOFF(cst));
#pragma unroll
            for (int ks2 = 0; ks2 < 4; ks2++) {
                uint32_t pa[4];
#pragma unroll
                for (int h = 0; h < 2; h++) {
                    const int nb = 2 * ks2 + h;
                    const int c0i = nb * 8 + 2 * tg;
                    float4 qq = *(const float4*)(st + c0i * 2);
                    __half2 h2a, h2b;
                    __builtin_memcpy(&h2a, &sh[nb][0], 4);
                    __builtin_memcpy(&h2b, &sh[nb][1], 4);
                    float2 s01 = __half22float2(h2a);
                    float2 s23 = __half22float2(h2b);
                    float p00 = pcalc(s01.x, qni0, tc0 * qq.y, qq.x, kf);
                    float p01 = pcalc(s01.y, qni0, tc0 * qq.w, qq.z, kf);
                    float p10 = pcalc(s23.x, qni1, tc1 * qq.y, qq.x, kf);
                    float p11 = pcalc(s23.y, qni1, tc1 * qq.w, qq.z, kf);
                    if (j0key + c0i     == gr0) p00 = 1.0f;
                    if (j0key + c0i + 1 == gr0) p01 = 1.0f;
                    if (j0key + c0i     == gr1) p10 = 1.0f;
                    if (j0key + c0i + 1 == gr1) p11 = 1.0f;
                    rsum0 += p00 + p01;
                    rsum1 += p10 + p11;
                    pa[h]     = pack_h2(p00, p01);
                    pa[2 + h] = pack_h2(p10, p11);
                }
#pragma unroll
                for (int np = 0; np < 16; np++) {
                    uint32_t b0, b1, b2, b3;
                    LDSM_X4T(b0, b1, b2, b3,
                             kbase + k2off + ks2 * (16 * KROWB) + np * 32);
                    hmma(of[2 * np],     pa[0], pa[2], pa[1], pa[3], b0, b1);
                    hmma(of[2 * np + 1], pa[0], pa[2], pa[1], pa[3], b2, b3);
                }
            }

            __syncwarp();
            if (lane == 0) mbar_arrive(su + MB_FREE(cst));
            if (++cst == 3) { cst = 0; cph ^= 1; }
        }

        // ---- segment epilogue: write O and l partial for slot ----
        rsum0 += __shfl_xor_sync(0xffffffffu, rsum0, 1);
        rsum0 += __shfl_xor_sync(0xffffffffu, rsum0, 2);
        rsum1 += __shfl_xor_sync(0xffffffffu, rsum1, 1);
        rsum1 += __shfl_xor_sync(0xffffffffu, rsum1, 2);

        const int slot = 2 * cta + seg;
        float* op0 = g_opart + ((size_t)slot << 15) + (size_t)(wbase + g) * DDIM;
        float* op1 = op0 + 8 * DDIM;
#pragma unroll
        for (int n = 0; n < 32; n++) {
            const int col = n * 8 + 2 * tg;
            *(float2*)(op0 + col) = make_float2(of[n][0], of[n][1]);
            *(float2*)(op1 + col) = make_float2(of[n][2], of[n][3]);
        }
        if (tg == 0) {
            g_lpart[slot * BM + wbase + g]     = rsum0;
            g_lpart[slot * BM + wbase + g + 8] = rsum1;
        }
        seg++;
    }
}

// ---------------- combine: sum static partial slots per qblock ----------------
__device__ __forceinline__ int ctaof(int jj) {
    return jj < 2912 ? jj / 56 : 52 + (jj - 2912) / 55;
}

__global__ void combine_kernel(float* __restrict__ out) {
    int idx = blockIdx.x * 256 + threadIdx.x;     // over 524288 float4s
    int r  = idx >> 6, c4 = idx & 63;
    int Q  = r >> 7, lr = r & 127;
    int clo = ctaof(Q << 7);
    int chi = ctaof((Q << 7) + 127);
    float l = 0.0f;
    float4 acc = make_float4(0.f, 0.f, 0.f, 0.f);
    for (int c = clo; c <= chi; c++) {
        int st = JSTART(c);
        int slot = 2 * c + (((st >> 7) == Q) ? 0 : 1);
        l += g_lpart[slot * BM + lr];
        float4 v = ((const float4*)(g_opart + ((size_t)slot << 15)
                                    + (size_t)lr * DDIM))[c4];
        acc.x += v.x; acc.y += v.y; acc.z += v.z; acc.w += v.w;
    }
    float inv = 1.0f / l;
    ((float4*)out)[idx] = make_float4(acc.x * inv, acc.y * inv,
                                      acc.z * inv, acc.w * inv);
}

extern "C" void kernel_launch(void* const* d_in, const int* in_sizes, int n_in,
                              void* d_out, int out_size) {
    const float* q  = (const float*)d_in[0];
    const float* cp = (const float*)d_in[1];
    float* out      = (float*)d_out;

    cudaFuncSetAttribute(hyp_fa_kernel,
                         cudaFuncAttributeMaxDynamicSharedMemorySize, SMEM_TOTAL);

    prep_kernel<<<NROWS / 8, 256>>>(q, cp);
    hyp_fa_kernel<<<NCTA, NTHREADS, SMEM_TOTAL>>>(cp);
    combine_kernel<<<2048, 256>>>(out);
}

// round 16
// speedup vs baseline: 2.5563x; 1.0765x over previous
#include <cuda_runtime.h>
#include <cuda_fp16.h>
#include <cstdint>

#define NROWS 8192
#define DDIM  256
#define BM    128
#define BN    64
#define EPSF  1e-6f
#define NTHREADS 544          // 16 compute warps + 1 loader warp
#define NCTA  148
// job partition: 8192 jobs = 52 CTAs x 56 + 96 CTAs x 55
#define JSTART(c) (55*(c) + ((c) < 52 ? (c) : 52))
#define JCNT(c)   ((c) < 52 ? 56 : 55)

// shared-memory layout in 32-bit WORDS
#define QW 132
#define KW 132
#define QOFF     0
#define KOFF(b)  (16896 + 8448*(b))    // three 64x132 K buffers
#define STOFF(b) (42240 + 128*(b))     // 64 float2 stats per buffer
#define PXOFF    42624                 // P exchange: [2 buf][8 pair][2 half][256 w]
#define PX(buf,pair,h) (PXOFF + (buf)*4096 + (pair)*512 + (h)*256)
#define MBARB    203264
#define SMEM_TOTAL 203312

#define KROWB 528

#define MB_FULL(b) (MBARB + 16*(b))
#define MB_FREE(b) (MBARB + 16*(b) + 8)

__device__ __half g_qh[(size_t)NROWS*DDIM];
__device__ float2 g_qt[NROWS];
__device__ float  g_opart[(size_t)2*NCTA*BM*DDIM];
__device__ float  g_lpart[2*NCTA*2*BM];

__device__ __forceinline__ float flg2(float x) {
    float r; asm("lg2.approx.f32 %0, %1;" : "=f"(r) : "f"(x)); return r;
}
__device__ __forceinline__ float fex2(float x) {
    float r; asm("ex2.approx.f32 %0, %1;" : "=f"(r) : "f"(x)); return r;
}
__device__ __forceinline__ float fsqrt_ap(float x) {
    float r; asm("sqrt.approx.f32 %0, %1;" : "=f"(r) : "f"(x)); return r;
}
__device__ __forceinline__ uint32_t pack_h2(float lo, float hi) {
    __half2 h = __floats2half2_rn(lo, hi);
    uint32_t u; __builtin_memcpy(&u, &h, 4); return u;
}
__device__ __forceinline__ void hmma(float d[4],
    uint32_t a0, uint32_t a1, uint32_t a2, uint32_t a3,
    uint32_t b0, uint32_t b1) {
    asm volatile(
        "mma.sync.aligned.m16n8k16.row.col.f32.f16.f16.f32 "
        "{%0,%1,%2,%3}, {%4,%5,%6,%7}, {%8,%9}, {%0,%1,%2,%3};\n"
        : "+f"(d[0]), "+f"(d[1]), "+f"(d[2]), "+f"(d[3])
        : "r"(a0), "r"(a1), "r"(a2), "r"(a3), "r"(b0), "r"(b1));
}
__device__ __forceinline__ void hmma16(uint32_t d[2],
    uint32_t a0, uint32_t a1, uint32_t a2, uint32_t a3,
    uint32_t b0, uint32_t b1) {
    asm volatile(
        "mma.sync.aligned.m16n8k16.row.col.f16.f16.f16.f16 "
        "{%0,%1}, {%2,%3,%4,%5}, {%6,%7}, {%0,%1};\n"
        : "+r"(d[0]), "+r"(d[1])
        : "r"(a0), "r"(a1), "r"(a2), "r"(a3), "r"(b0), "r"(b1));
}
#define LDSM_X4(r0,r1,r2,r3,a) asm volatile( \
    "ldmatrix.sync.aligned.m8n8.x4.shared.b16 {%0,%1,%2,%3}, [%4];" \
    : "=r"(r0),"=r"(r1),"=r"(r2),"=r"(r3) : "r"(a))
#define LDSM_X4T(r0,r1,r2,r3,a) asm volatile( \
    "ldmatrix.sync.aligned.m8n8.x4.trans.shared.b16 {%0,%1,%2,%3}, [%4];" \
    : "=r"(r0),"=r"(r1),"=r"(r2),"=r"(r3) : "r"(a))
__device__ __forceinline__ void cpa16(uint32_t dst, const void* src) {
    asm volatile("cp.async.cg.shared.global [%0], [%1], 16;"
                 :: "r"(dst), "l"(src) : "memory");
}
#define CPA_COMMIT() asm volatile("cp.async.commit_group;" ::: "memory")
#define CPA_WAIT0()  asm volatile("cp.async.wait_group 0;" ::: "memory")
#define CPA_WAIT1()  asm volatile("cp.async.wait_group 1;" ::: "memory")
#define FENCE_PROXY() asm volatile("fence.proxy.async.shared::cta;" ::: "memory")
#define CBAR() asm volatile("bar.sync 1, 512;" ::: "memory")   // 16 compute warps
#define PBAR(id) asm volatile("bar.sync %0, 64;" :: "r"(id) : "memory")

__device__ __forceinline__ void mbar_init(uint32_t a, uint32_t c) {
    asm volatile("mbarrier.init.shared.b64 [%0], %1;" :: "r"(a), "r"(c) : "memory");
}
__device__ __forceinline__ void mbar_arrive(uint32_t a) {
    asm volatile("mbarrier.arrive.shared.b64 _, [%0];" :: "r"(a) : "memory");
}
__device__ __forceinline__ void mbar_wait(uint32_t a, uint32_t ph) {
    asm volatile(
        "{\n\t.reg .pred P1;\n\t"
        "W%=:\n\t"
        "mbarrier.try_wait.parity.acquire.cta.shared::cta.b64 P1, [%0], %1, 0x989680;\n\t"
        "@P1 bra.uni D%=;\n\t"
        "bra.uni W%=;\n\t"
        "D%=:\n\t}"
        :: "r"(a), "r"(ph) : "memory");
}

// ---------------- prep: half copy + row stats ----------------
__global__ void prep_kernel(const float* __restrict__ q, const float* __restrict__ cp) {
    int row  = blockIdx.x * 8 + (threadIdx.x >> 5);
    int lane = threadIdx.x & 31;
    const float4* qr = (const float4*)(q + (size_t)row * DDIM);
    float4 A = qr[lane * 2], B = qr[lane * 2 + 1];
    __half h[8];
    h[0]=__float2half_rn(A.x); h[1]=__float2half_rn(A.y);
    h[2]=__float2half_rn(A.z); h[3]=__float2half_rn(A.w);
    h[4]=__float2half_rn(B.x); h[5]=__float2half_rn(B.y);
    h[6]=__float2half_rn(B.z); h[7]=__float2half_rn(B.w);
    float s = 0.0f;
#pragma unroll
    for (int i = 0; i < 8; i++) { float r = __half2float(h[i]); s += r * r; }
    uint32_t* wr = (uint32_t*)(g_qh + (size_t)row * DDIM + lane * 8);
#pragma unroll
    for (int i = 0; i < 4; i++) {
        __half2 p = __halves2half2(h[2*i], h[2*i+1]);
        uint32_t u; __builtin_memcpy(&u, &p, 4); wr[i] = u;
    }
#pragma unroll
    for (int o = 16; o > 0; o >>= 1) s += __shfl_xor_sync(0xffffffffu, s, o);
    if (lane == 0) {
        float cc = fmaxf(*cp, EPSF);
        g_qt[row] = make_float2(s, 1.0f / fmaxf(1.0f - cc * s, EPSF));
    }
}

__device__ __forceinline__ float pcalc(float s, float qni, float coef,
                                       float qnj, float kf) {
    float diff = fmaxf(qni + qnj - 2.0f * s, 0.0f);
    float arg  = fmaf(coef, diff, 1.0f);
    arg = fmaxf(arg, 1.0f + EPSF) + EPSF;
    float x = arg - 1.0f;
    float y = arg + fsqrt_ap(x * (arg + 1.0f));
    return fex2(-kf * flg2(y));
}

// ---------------- main kernel ----------------
__global__ void __launch_bounds__(NTHREADS, 1)
hyp_fa_kernel(const float* __restrict__ cp) {
    extern __shared__ uint32_t sw[];
    uint32_t su;
    asm("{ .reg .u64 t; cvta.to.shared.u64 t, %1; cvt.u32.u64 %0, t; }"
        : "=r"(su) : "l"(sw));

    const int tid  = threadIdx.x;
    const int w    = tid >> 5;            // 0..15 compute, 16 loader
    const int lane = tid & 31;
    const int g    = lane >> 2;
    const int tg   = lane & 3;
    const int cta  = blockIdx.x;
    const int jstart = JSTART(cta);
    const int jcnt   = JCNT(cta);

    const float ccv = fmaxf(*cp, EPSF);
    const float kf  = 1.0f / sqrtf(ccv);

    if (tid == 0) {
#pragma unroll
        for (int b = 0; b < 3; b++) {
            mbar_init(su + MB_FULL(b), 1);
            mbar_init(su + MB_FREE(b), 16);
        }
    }
    __syncthreads();

    // ================= loader warp =================
    if (w == 16) {
        int pph = 1, pst = 0, prev = 0;
        for (int jt = 0; jt < jcnt; jt++) {
            mbar_wait(su + MB_FREE(pst), pph);
            const int kb = ((jstart + jt) & 127) << 6;
            const uint32_t kdst = su + (uint32_t)KOFF(pst) * 4;
#pragma unroll
            for (int i = 0; i < 64; i++) {
                int f = i * 32 + lane;
                int r = f >> 5, c = f & 31;
                cpa16(kdst + (uint32_t)(r * KW + c * 4) * 4,
                      g_qh + ((size_t)(kb + r) << 8) + c * 8);
            }
            cpa16(su + (uint32_t)(STOFF(pst) + lane * 4) * 4,
                  (const float*)(g_qt + kb) + lane * 4);
            CPA_COMMIT();
            if (jt > 0) {
                CPA_WAIT1();
                FENCE_PROXY();
                if (lane == 0) mbar_arrive(su + MB_FULL(prev));
            }
            prev = pst;
            if (++pst == 3) { pst = 0; pph ^= 1; }
        }
        CPA_WAIT0();
        FENCE_PROXY();
        if (lane == 0) mbar_arrive(su + MB_FULL(prev));
        return;
    }

    // ================= compute warps =================
    const int pair  = w >> 1;             // 0..7 -> rows [16*pair, +16)
    const int hf    = w & 1;              // key-half + d-half
    const int wbase = pair * 16;

    const uint32_t qlb = su
        + (uint32_t)(wbase + (lane & 7) + 8 * ((lane >> 3) & 1)) * KROWB
        + (uint32_t)(lane >> 4) * 16;
    const uint32_t k1off =
        (uint32_t)((lane & 7) + 8 * (lane >> 4)) * KROWB
        + (uint32_t)((lane >> 3) & 1) * 16
        + (uint32_t)hf * (32 * KROWB);                 // this warp's 32 keys
    const uint32_t k2off =
        (uint32_t)((lane & 7) + 8 * ((lane >> 3) & 1)) * KROWB
        + (uint32_t)(lane >> 4) * 16
        + (uint32_t)hf * 256;                          // this warp's 128 d-cols

    const uint32_t pxw = su + (uint32_t)(PX(0, 0, 0) + pair * 512 + hf * 256
                                         + lane * 4) * 4;
    const uint32_t pxr = su + (uint32_t)(PX(0, 0, 0) + pair * 512 + (1 - hf) * 256
                                         + lane * 4) * 4;
    const int barid = 2 + pair;

    int cst = 0, cph = 0;
    int j = jstart;
    const int jend = jstart + jcnt;
    int seg = 0;

    while (j < jend) {
        const int Q = j >> 7;
        const int segend = (jend < ((Q + 1) << 7)) ? jend : ((Q + 1) << 7);

        // ---- (re)load Q tile for qblock Q ----
        CBAR();
#pragma unroll
        for (int i = 0; i < 8; i++) {
            int f = tid + i * 512;
            int r = f >> 5, c = f & 31;
            cpa16(su + (QOFF + r * QW + c * 4) * 4,
                  g_qh + ((size_t)(Q * BM + r) << 8) + c * 8);
        }
        CPA_COMMIT(); CPA_WAIT0();
        CBAR();

        const int gr0 = (Q << 7) + wbase + g;
        const int gr1 = gr0 + 8;
        const float2 qt0 = g_qt[gr0], qt1 = g_qt[gr1];
        const float qni0 = qt0.x, qni1 = qt1.x;
        const float tc0 = 2.0f * ccv * qt0.y;
        const float tc1 = 2.0f * ccv * qt1.y;

        float of[16][4];
#pragma unroll
        for (int n = 0; n < 16; n++)
#pragma unroll
            for (int e = 0; e < 4; e++) of[n][e] = 0.0f;
        float rsum0 = 0.0f, rsum1 = 0.0f;

        for (; j < segend; j++) {
            mbar_wait(su + MB_FULL(cst), cph);
            const uint32_t kbase = su + (uint32_t)KOFF(cst) * 4;
            const int j0key = (j & 127) << 6;
            const uint32_t pxb = (uint32_t)(j & 1) * (4096 * 4);

            // ---- GEMM1: S(16 x 32keys) = Q . K^T (f16 accumulators) ----
            uint32_t sh[4][2];
#pragma unroll
            for (int n = 0; n < 4; n++) { sh[n][0] = 0u; sh[n][1] = 0u; }
#pragma unroll
            for (int ks = 0; ks < 16; ks++) {
                uint32_t a0, a1, a2, a3;
                LDSM_X4(a0, a1, a2, a3, qlb + ks * 32);
#pragma unroll
                for (int nbp = 0; nbp < 2; nbp++) {
                    uint32_t b0, b1, b2, b3;
                    LDSM_X4(b0, b1, b2, b3,
                            kbase + k1off + nbp * (16 * KROWB) + ks * 32);
                    hmma16(sh[2 * nbp],     a0, a1, a2, a3, b0, b1);
                    hmma16(sh[2 * nbp + 1], a0, a1, a2, a3, b2, b3);
                }
            }

            // ---- transform: own 32 keys ----
            const float* st = (const float*)(sw + STOFF(cst));
            uint32_t pown[2][4];
#pragma unroll
            for (int nb = 0; nb < 4; nb++) {
                const int c0i = 32 * hf + nb * 8 + 2 * tg;
                float4 qq = *(const float4*)(st + c0i * 2);
                __half2 h2a, h2b;
                __builtin_memcpy(&h2a, &sh[nb][0], 4);
                __builtin_memcpy(&h2b, &sh[nb][1], 4);
                float2 s01 = __half22float2(h2a);
                float2 s23 = __half22float2(h2b);
                float p00 = pcalc(s01.x, qni0, tc0 * qq.y, qq.x, kf);
                float p01 = pcalc(s01.y, qni0, tc0 * qq.w, qq.z, kf);
                float p10 = pcalc(s23.x, qni1, tc1 * qq.y, qq.x, kf);
                float p11 = pcalc(s23.y, qni1, tc1 * qq.w, qq.z, kf);
                if (j0key + c0i     == gr0) p00 = 1.0f;
                if (j0key + c0i + 1 == gr0) p01 = 1.0f;
                if (j0key + c0i     == gr1) p10 = 1.0f;
                if (j0key + c0i + 1 == gr1) p11 = 1.0f;
                rsum0 += p00 + p01;
                rsum1 += p10 + p11;
                pown[nb >> 1][nb & 1]       = pack_h2(p00, p01);
                pown[nb >> 1][2 + (nb & 1)] = pack_h2(p10, p11);
            }

            // ---- exchange P halves with pair warp ----
            asm volatile("st.shared.v4.b32 [%0], {%1,%2,%3,%4};"
                :: "r"(pxw + pxb), "r"(pown[0][0]), "r"(pown[0][1]),
                   "r"(pown[0][2]), "r"(pown[0][3]) : "memory");
            asm volatile("st.shared.v4.b32 [%0], {%1,%2,%3,%4};"
                :: "r"(pxw + pxb + 512), "r"(pown[1][0]), "r"(pown[1][1]),
                   "r"(pown[1][2]), "r"(pown[1][3]) : "memory");
            PBAR(barid);
            uint32_t F0[4], F1[4];
            asm volatile("ld.shared.v4.b32 {%0,%1,%2,%3}, [%4];"
                : "=r"(F0[0]), "=r"(F0[1]), "=r"(F0[2]), "=r"(F0[3])
                : "r"(pxr + pxb));
            asm volatile("ld.shared.v4.b32 {%0,%1,%2,%3}, [%4];"
                : "=r"(F1[0]), "=r"(F1[1]), "=r"(F1[2]), "=r"(F1[3])
                : "r"(pxr + pxb + 512));

            // ---- GEMM2: O(16 x 128d) += P(16x64) . V ----
            const int fks = 2 * (1 - hf);
#pragma unroll
            for (int q2 = 0; q2 < 2; q2++) {
                const uint32_t* W = q2 ? F1 : F0;
                const int ks2 = fks + q2;
#pragma unroll
                for (int np = 0; np < 8; np++) {
                    uint32_t b0, b1, b2, b3;
                    LDSM_X4T(b0, b1, b2, b3,
                             kbase + k2off + ks2 * (16 * KROWB) + np * 32);
                    hmma(of[2 * np],     W[0], W[2], W[1], W[3], b0, b1);
                    hmma(of[2 * np + 1], W[0], W[2], W[1], W[3], b2, b3);
                }
            }
            const int oks = 2 * hf;
#pragma unroll
            for (int q2 = 0; q2 < 2; q2++) {
                const uint32_t* W = pown[q2];
                const int ks2 = oks + q2;
#pragma unroll
                for (int np = 0; np < 8; np++) {
                    uint32_t b0, b1, b2, b3;
                    LDSM_X4T(b0, b1, b2, b3,
                             kbase + k2off + ks2 * (16 * KROWB) + np * 32);
                    hmma(of[2 * np],     W[0], W[2], W[1], W[3], b0, b1);
                    hmma(of[2 * np + 1], W[0], W[2], W[1], W[3], b2, b3);
                }
            }

            __syncwarp();
            if (lane == 0) mbar_arrive(su + MB_FREE(cst));
            if (++cst == 3) { cst = 0; cph ^= 1; }
        }

        // ---- segment epilogue ----
        rsum0 += __shfl_xor_sync(0xffffffffu, rsum0, 1);
        rsum0 += __shfl_xor_sync(0xffffffffu, rsum0, 2);
        rsum1 += __shfl_xor_sync(0xffffffffu, rsum1, 1);
        rsum1 += __shfl_xor_sync(0xffffffffu, rsum1, 2);

        const int slot = 2 * cta + seg;
        float* op0 = g_opart + ((size_t)slot << 15) + (size_t)(wbase + g) * DDIM
                   + hf * 128;
        float* op1 = op0 + 8 * DDIM;
#pragma unroll
        for (int n = 0; n < 16; n++) {
            const int col = n * 8 + 2 * tg;
            *(float2*)(op0 + col) = make_float2(of[n][0], of[n][1]);
            *(float2*)(op1 + col) = make_float2(of[n][2], of[n][3]);
        }
        if (tg == 0) {
            g_lpart[slot * 2 * BM + hf * BM + wbase + g]     = rsum0;
            g_lpart[slot * 2 * BM + hf * BM + wbase + g + 8] = rsum1;
        }
        seg++;
    }
}

// ---------------- combine: sum static partial slots per qblock ----------------
__device__ __forceinline__ int ctaof(int jj) {
    return jj < 2912 ? jj / 56 : 52 + (jj - 2912) / 55;
}

__global__ void combine_kernel(float* __restrict__ out) {
    int idx = blockIdx.x * 256 + threadIdx.x;     // over 524288 float4s
    int r  = idx >> 6, c4 = idx & 63;
    int Q  = r >> 7, lr = r & 127;
    int clo = ctaof(Q << 7);
    int chi = ctaof((Q << 7) + 127);
    float l = 0.0f;
    float4 acc = make_float4(0.f, 0.f, 0.f, 0.f);
    for (int c = clo; c <= chi; c++) {
        int st = JSTART(c);
        int slot = 2 * c + (((st >> 7) == Q) ? 0 : 1);
        l += g_lpart[slot * 2 * BM + lr] + g_lpart[slot * 2 * BM + BM + lr];
        float4 v = ((const float4*)(g_opart + ((size_t)slot << 15)
                                    + (size_t)lr * DDIM))[c4];
        acc.x += v.x; acc.y += v.y; acc.z += v.z; acc.w += v.w;
    }
    float inv = 1.0f / l;
    ((float4*)out)[idx] = make_float4(acc.x * inv, acc.y * inv,
                                      acc.z * inv, acc.w * inv);
}

extern "C" void kernel_launch(void* const* d_in, const int* in_sizes, int n_in,
                              void* d_out, int out_size) {
    const float* q  = (const float*)d_in[0];
    const float* cp = (const float*)d_in[1];
    float* out      = (float*)d_out;

    cudaFuncSetAttribute(hyp_fa_kernel,
                         cudaFuncAttributeMaxDynamicSharedMemorySize, SMEM_TOTAL);

    prep_kernel<<<NROWS / 8, 256>>>(q, cp);
    hyp_fa_kernel<<<NCTA, NTHREADS, SMEM_TOTAL>>>(cp);
    combine_kernel<<<2048, 256>>>(out);
}

// round 17
// speedup vs baseline: 2.6244x; 1.0267x over previous
#include <cuda_runtime.h>
#include <cuda_fp16.h>
#include <cstdint>

#define NROWS 8192
#define DDIM  256
#define BM    128
#define BN    64
#define EPSF  1e-6f
#define NTHREADS 544          // 16 compute warps + 1 loader warp
#define NCTA  148
// job partition: 8192 jobs = 52 CTAs x 56 + 96 CTAs x 55
#define JSTART(c) (55*(c) + ((c) < 52 ? (c) : 52))
#define JCNT(c)   ((c) < 52 ? 56 : 55)

// shared-memory layout in 32-bit WORDS
#define QW 132
#define KW 132
#define QOFF     0
#define KOFF(b)  (16896 + 8448*(b))    // three 64x132 K buffers
#define STOFF(b) (42240 + 128*(b))     // 64 float2 stats per buffer
#define PXOFF    42624                 // P exchange: [2 buf][8 pair][2 half][256 w]
#define PX(buf,pair,h) (PXOFF + (buf)*4096 + (pair)*512 + (h)*256)
#define MBARB    203264
#define SMEM_TOTAL 203312

#define KROWB 528

#define MB_FULL(b) (MBARB + 16*(b))
#define MB_FREE(b) (MBARB + 16*(b) + 8)

__device__ __half g_qh[(size_t)NROWS*DDIM];
__device__ float2 g_qt[NROWS];
__device__ float  g_opart[(size_t)2*NCTA*BM*DDIM];
__device__ float  g_lpart[2*NCTA*2*BM];

__device__ __forceinline__ float flg2(float x) {
    float r; asm("lg2.approx.f32 %0, %1;" : "=f"(r) : "f"(x)); return r;
}
__device__ __forceinline__ float fex2(float x) {
    float r; asm("ex2.approx.f32 %0, %1;" : "=f"(r) : "f"(x)); return r;
}
__device__ __forceinline__ float fsqrt_ap(float x) {
    float r; asm("sqrt.approx.f32 %0, %1;" : "=f"(r) : "f"(x)); return r;
}
__device__ __forceinline__ uint32_t pack_h2(float lo, float hi) {
    __half2 h = __floats2half2_rn(lo, hi);
    uint32_t u; __builtin_memcpy(&u, &h, 4); return u;
}
__device__ __forceinline__ void hmma(float d[4],
    uint32_t a0, uint32_t a1, uint32_t a2, uint32_t a3,
    uint32_t b0, uint32_t b1) {
    asm volatile(
        "mma.sync.aligned.m16n8k16.row.col.f32.f16.f16.f32 "
        "{%0,%1,%2,%3}, {%4,%5,%6,%7}, {%8,%9}, {%0,%1,%2,%3};\n"
        : "+f"(d[0]), "+f"(d[1]), "+f"(d[2]), "+f"(d[3])
        : "r"(a0), "r"(a1), "r"(a2), "r"(a3), "r"(b0), "r"(b1));
}
__device__ __forceinline__ void hmma16(uint32_t d[2],
    uint32_t a0, uint32_t a1, uint32_t a2, uint32_t a3,
    uint32_t b0, uint32_t b1) {
    asm volatile(
        "mma.sync.aligned.m16n8k16.row.col.f16.f16.f16.f16 "
        "{%0,%1}, {%2,%3,%4,%5}, {%6,%7}, {%0,%1};\n"
        : "+r"(d[0]), "+r"(d[1])
        : "r"(a0), "r"(a1), "r"(a2), "r"(a3), "r"(b0), "r"(b1));
}
#define LDSM_X4(r0,r1,r2,r3,a) asm volatile( \
    "ldmatrix.sync.aligned.m8n8.x4.shared.b16 {%0,%1,%2,%3}, [%4];" \
    : "=r"(r0),"=r"(r1),"=r"(r2),"=r"(r3) : "r"(a))
#define LDSM_X4T(r0,r1,r2,r3,a) asm volatile( \
    "ldmatrix.sync.aligned.m8n8.x4.trans.shared.b16 {%0,%1,%2,%3}, [%4];" \
    : "=r"(r0),"=r"(r1),"=r"(r2),"=r"(r3) : "r"(a))
__device__ __forceinline__ void cpa16(uint32_t dst, const void* src) {
    asm volatile("cp.async.cg.shared.global [%0], [%1], 16;"
                 :: "r"(dst), "l"(src) : "memory");
}
#define CPA_COMMIT() asm volatile("cp.async.commit_group;" ::: "memory")
#define CPA_WAIT0()  asm volatile("cp.async.wait_group 0;" ::: "memory")
#define CPA_WAIT1()  asm volatile("cp.async.wait_group 1;" ::: "memory")
#define FENCE_PROXY() asm volatile("fence.proxy.async.shared::cta;" ::: "memory")
#define CBAR() asm volatile("bar.sync 1, 512;" ::: "memory")
#define PBAR(id) asm volatile("bar.sync %0, 64;" :: "r"(id) : "memory")

__device__ __forceinline__ void mbar_init(uint32_t a, uint32_t c) {
    asm volatile("mbarrier.init.shared.b64 [%0], %1;" :: "r"(a), "r"(c) : "memory");
}
__device__ __forceinline__ void mbar_arrive(uint32_t a) {
    asm volatile("mbarrier.arrive.shared.b64 _, [%0];" :: "r"(a) : "memory");
}
__device__ __forceinline__ void mbar_wait(uint32_t a, uint32_t ph) {
    asm volatile(
        "{\n\t.reg .pred P1;\n\t"
        "W%=:\n\t"
        "mbarrier.try_wait.parity.acquire.cta.shared::cta.b64 P1, [%0], %1, 0x989680;\n\t"
        "@P1 bra.uni D%=;\n\t"
        "bra.uni W%=;\n\t"
        "D%=:\n\t}"
        :: "r"(a), "r"(ph) : "memory");
}

// ---------------- prep: half copy + row stats ----------------
__global__ void prep_kernel(const float* __restrict__ q, const float* __restrict__ cp) {
    int row  = blockIdx.x * 8 + (threadIdx.x >> 5);
    int lane = threadIdx.x & 31;
    const float4* qr = (const float4*)(q + (size_t)row * DDIM);
    float4 A = qr[lane * 2], B = qr[lane * 2 + 1];
    __half h[8];
    h[0]=__float2half_rn(A.x); h[1]=__float2half_rn(A.y);
    h[2]=__float2half_rn(A.z); h[3]=__float2half_rn(A.w);
    h[4]=__float2half_rn(B.x); h[5]=__float2half_rn(B.y);
    h[6]=__float2half_rn(B.z); h[7]=__float2half_rn(B.w);
    float s = 0.0f;
#pragma unroll
    for (int i = 0; i < 8; i++) { float r = __half2float(h[i]); s += r * r; }
    uint32_t* wr = (uint32_t*)(g_qh + (size_t)row * DDIM + lane * 8);
#pragma unroll
    for (int i = 0; i < 4; i++) {
        __half2 p = __halves2half2(h[2*i], h[2*i+1]);
        uint32_t u; __builtin_memcpy(&u, &p, 4); wr[i] = u;
    }
#pragma unroll
    for (int o = 16; o > 0; o >>= 1) s += __shfl_xor_sync(0xffffffffu, s, o);
    if (lane == 0) {
        float cc = fmaxf(*cp, EPSF);
        g_qt[row] = make_float2(s, 1.0f / fmaxf(1.0f - cc * s, EPSF));
    }
}

__device__ __forceinline__ float pcalc(float s, float qni, float coef,
                                       float qnj, float kf) {
    float diff = fmaxf(qni + qnj - 2.0f * s, 0.0f);
    float arg  = fmaf(coef, diff, 1.0f);
    arg = fmaxf(arg, 1.0f + EPSF) + EPSF;
    float x = arg - 1.0f;
    float y = arg + fsqrt_ap(x * (arg + 1.0f));
    return fex2(-kf * flg2(y));
}

// ---------------- main kernel ----------------
__global__ void __launch_bounds__(NTHREADS, 1)
hyp_fa_kernel(const float* __restrict__ cp) {
    extern __shared__ uint32_t sw[];
    uint32_t su;
    asm("{ .reg .u64 t; cvta.to.shared.u64 t, %1; cvt.u32.u64 %0, t; }"
        : "=r"(su) : "l"(sw));

    const int tid  = threadIdx.x;
    const int w    = tid >> 5;            // 0..15 compute, 16 loader
    const int lane = tid & 31;
    const int g    = lane >> 2;
    const int tg   = lane & 3;
    const int cta  = blockIdx.x;
    const int jstart = JSTART(cta);
    const int jcnt   = JCNT(cta);

    const float ccv = fmaxf(*cp, EPSF);
    const float kf  = 1.0f / sqrtf(ccv);

    if (tid == 0) {
#pragma unroll
        for (int b = 0; b < 3; b++) {
            mbar_init(su + MB_FULL(b), 1);
            mbar_init(su + MB_FREE(b), 16);
        }
    }
    __syncthreads();

    // ================= loader warp =================
    if (w == 16) {
        int pph = 1, pst = 0, prev = 0;
        for (int jt = 0; jt < jcnt; jt++) {
            mbar_wait(su + MB_FREE(pst), pph);
            const int kb = ((jstart + jt) & 127) << 6;
            const uint32_t kdst = su + (uint32_t)KOFF(pst) * 4;
#pragma unroll
            for (int i = 0; i < 64; i++) {
                int f = i * 32 + lane;
                int r = f >> 5, c = f & 31;
                cpa16(kdst + (uint32_t)(r * KW + c * 4) * 4,
                      g_qh + ((size_t)(kb + r) << 8) + c * 8);
            }
            cpa16(su + (uint32_t)(STOFF(pst) + lane * 4) * 4,
                  (const float*)(g_qt + kb) + lane * 4);
            CPA_COMMIT();
            if (jt > 0) {
                CPA_WAIT1();
                FENCE_PROXY();
                if (lane == 0) mbar_arrive(su + MB_FULL(prev));
            }
            prev = pst;
            if (++pst == 3) { pst = 0; pph ^= 1; }
        }
        CPA_WAIT0();
        FENCE_PROXY();
        if (lane == 0) mbar_arrive(su + MB_FULL(prev));
        return;
    }

    // ================= compute warps =================
    const int pair  = w >> 1;             // rows [16*pair, +16)
    const int hf    = w & 1;              // key-half + d-half
    const int wbase = pair * 16;

    const uint32_t qlb = su
        + (uint32_t)(wbase + (lane & 7) + 8 * ((lane >> 3) & 1)) * KROWB
        + (uint32_t)(lane >> 4) * 16;
    const uint32_t k1off =
        (uint32_t)((lane & 7) + 8 * (lane >> 4)) * KROWB
        + (uint32_t)((lane >> 3) & 1) * 16
        + (uint32_t)hf * (32 * KROWB);
    const uint32_t k2off =
        (uint32_t)((lane & 7) + 8 * ((lane >> 3) & 1)) * KROWB
        + (uint32_t)(lane >> 4) * 16
        + (uint32_t)hf * 256;

    const uint32_t pxw = su + (uint32_t)(PX(0, 0, 0) + pair * 512 + hf * 256
                                         + lane * 4) * 4;
    const uint32_t pxr = su + (uint32_t)(PX(0, 0, 0) + pair * 512 + (1 - hf) * 256
                                         + lane * 4) * 4;
    const int barid = 2 + pair;

    int cst = 0, cph = 0;
    int j = jstart;
    const int jend = jstart + jcnt;
    int seg = 0;

    while (j < jend) {
        const int Q = j >> 7;
        const int segend = (jend < ((Q + 1) << 7)) ? jend : ((Q + 1) << 7);

        // ---- (re)load Q tile for qblock Q ----
        CBAR();
#pragma unroll
        for (int i = 0; i < 8; i++) {
            int f = tid + i * 512;
            int r = f >> 5, c = f & 31;
            cpa16(su + (QOFF + r * QW + c * 4) * 4,
                  g_qh + ((size_t)(Q * BM + r) << 8) + c * 8);
        }
        CPA_COMMIT(); CPA_WAIT0();
        CBAR();

        const int gr0 = (Q << 7) + wbase + g;
        const int gr1 = gr0 + 8;
        const float2 qt0 = g_qt[gr0], qt1 = g_qt[gr1];
        const float qni0 = qt0.x, qni1 = qt1.x;
        const float tc0 = 2.0f * ccv * qt0.y;
        const float tc1 = 2.0f * ccv * qt1.y;

        float of[16][4];
#pragma unroll
        for (int n = 0; n < 16; n++)
#pragma unroll
            for (int e = 0; e < 4; e++) of[n][e] = 0.0f;
        float rsum0 = 0.0f, rsum1 = 0.0f;

        for (; j < segend; j++) {
            mbar_wait(su + MB_FULL(cst), cph);
            const uint32_t kbase = su + (uint32_t)KOFF(cst) * 4;
            const int j0key = (j & 127) << 6;
            const uint32_t pxb = (uint32_t)(j & 1) * (4096 * 4);

            // ---- GEMM1: S(16 x 32keys) = Q . K^T (f16 accumulators) ----
            uint32_t sh[4][2];
#pragma unroll
            for (int n = 0; n < 4; n++) { sh[n][0] = 0u; sh[n][1] = 0u; }
#pragma unroll
            for (int ks = 0; ks < 16; ks++) {
                uint32_t a0, a1, a2, a3;
                LDSM_X4(a0, a1, a2, a3, qlb + ks * 32);
#pragma unroll
                for (int nbp = 0; nbp < 2; nbp++) {
                    uint32_t b0, b1, b2, b3;
                    LDSM_X4(b0, b1, b2, b3,
                            kbase + k1off + nbp * (16 * KROWB) + ks * 32);
                    hmma16(sh[2 * nbp],     a0, a1, a2, a3, b0, b1);
                    hmma16(sh[2 * nbp + 1], a0, a1, a2, a3, b2, b3);
                }
            }

            // ---- transform: own 32 keys ----
            const float* st = (const float*)(sw + STOFF(cst));
            uint32_t pown[2][4];
#pragma unroll
            for (int nb = 0; nb < 4; nb++) {
                const int c0i = 32 * hf + nb * 8 + 2 * tg;
                float4 qq = *(const float4*)(st + c0i * 2);
                __half2 h2a, h2b;
                __builtin_memcpy(&h2a, &sh[nb][0], 4);
                __builtin_memcpy(&h2b, &sh[nb][1], 4);
                float2 s01 = __half22float2(h2a);
                float2 s23 = __half22float2(h2b);
                float p00 = pcalc(s01.x, qni0, tc0 * qq.y, qq.x, kf);
                float p01 = pcalc(s01.y, qni0, tc0 * qq.w, qq.z, kf);
                float p10 = pcalc(s23.x, qni1, tc1 * qq.y, qq.x, kf);
                float p11 = pcalc(s23.y, qni1, tc1 * qq.w, qq.z, kf);
                if (j0key + c0i     == gr0) p00 = 1.0f;
                if (j0key + c0i + 1 == gr0) p01 = 1.0f;
                if (j0key + c0i     == gr1) p10 = 1.0f;
                if (j0key + c0i + 1 == gr1) p11 = 1.0f;
                rsum0 += p00 + p01;
                rsum1 += p10 + p11;
                pown[nb >> 1][nb & 1]       = pack_h2(p00, p01);
                pown[nb >> 1][2 + (nb & 1)] = pack_h2(p10, p11);
            }

            // ---- publish own P halves, then hide partner latency behind
            //      the own-half GEMM2 before the pair barrier ----
            asm volatile("st.shared.v4.b32 [%0], {%1,%2,%3,%4};"
                :: "r"(pxw + pxb), "r"(pown[0][0]), "r"(pown[0][1]),
                   "r"(pown[0][2]), "r"(pown[0][3]) : "memory");
            asm volatile("st.shared.v4.b32 [%0], {%1,%2,%3,%4};"
                :: "r"(pxw + pxb + 512), "r"(pown[1][0]), "r"(pown[1][1]),
                   "r"(pown[1][2]), "r"(pown[1][3]) : "memory");

            // ---- GEMM2 (own keys) ----
            const int oks = 2 * hf;
#pragma unroll
            for (int q2 = 0; q2 < 2; q2++) {
                const uint32_t* W = pown[q2];
                const int ks2 = oks + q2;
#pragma unroll
                for (int np = 0; np < 8; np++) {
                    uint32_t b0, b1, b2, b3;
                    LDSM_X4T(b0, b1, b2, b3,
                             kbase + k2off + ks2 * (16 * KROWB) + np * 32);
                    hmma(of[2 * np],     W[0], W[2], W[1], W[3], b0, b1);
                    hmma(of[2 * np + 1], W[0], W[2], W[1], W[3], b2, b3);
                }
            }

            PBAR(barid);
            uint32_t F0[4], F1[4];
            asm volatile("ld.shared.v4.b32 {%0,%1,%2,%3}, [%4];"
                : "=r"(F0[0]), "=r"(F0[1]), "=r"(F0[2]), "=r"(F0[3])
                : "r"(pxr + pxb));
            asm volatile("ld.shared.v4.b32 {%0,%1,%2,%3}, [%4];"
                : "=r"(F1[0]), "=r"(F1[1]), "=r"(F1[2]), "=r"(F1[3])
                : "r"(pxr + pxb + 512));

            // ---- GEMM2 (partner's keys) ----
            const int fks = 2 * (1 - hf);
#pragma unroll
            for (int q2 = 0; q2 < 2; q2++) {
                const uint32_t* W = q2 ? F1 : F0;
                const int ks2 = fks + q2;
#pragma unroll
                for (int np = 0; np < 8; np++) {
                    uint32_t b0, b1, b2, b3;
                    LDSM_X4T(b0, b1, b2, b3,
                             kbase + k2off + ks2 * (16 * KROWB) + np * 32);
                    hmma(of[2 * np],     W[0], W[2], W[1], W[3], b0, b1);
                    hmma(of[2 * np + 1], W[0], W[2], W[1], W[3], b2, b3);
                }
            }

            __syncwarp();
            if (lane == 0) mbar_arrive(su + MB_FREE(cst));
            if (++cst == 3) { cst = 0; cph ^= 1; }
        }

        // ---- segment epilogue ----
        rsum0 += __shfl_xor_sync(0xffffffffu, rsum0, 1);
        rsum0 += __shfl_xor_sync(0xffffffffu, rsum0, 2);
        rsum1 += __shfl_xor_sync(0xffffffffu, rsum1, 1);
        rsum1 += __shfl_xor_sync(0xffffffffu, rsum1, 2);

        const int slot = 2 * cta + seg;
        float* op0 = g_opart + ((size_t)slot << 15) + (size_t)(wbase + g) * DDIM
                   + hf * 128;
        float* op1 = op0 + 8 * DDIM;
#pragma unroll
        for (int n = 0; n < 16; n++) {
            const int col = n * 8 + 2 * tg;
            *(float2*)(op0 + col) = make_float2(of[n][0], of[n][1]);
            *(float2*)(op1 + col) = make_float2(of[n][2], of[n][3]);
        }
        if (tg == 0) {
            g_lpart[slot * 2 * BM + hf * BM + wbase + g]     = rsum0;
            g_lpart[slot * 2 * BM + hf * BM + wbase + g + 8] = rsum1;
        }
        seg++;
    }
}

// ---------------- combine: sum static partial slots per qblock ----------------
__device__ __forceinline__ int ctaof(int jj) {
    return jj < 2912 ? jj / 56 : 52 + (jj - 2912) / 55;
}

__global__ void combine_kernel(float* __restrict__ out) {
    int idx = blockIdx.x * 256 + threadIdx.x;     // over 524288 float4s
    int r  = idx >> 6, c4 = idx & 63;
    int Q  = r >> 7, lr = r & 127;
    int clo = ctaof(Q << 7);
    int chi = ctaof((Q << 7) + 127);
    float l = 0.0f;
    float4 acc = make_float4(0.f, 0.f, 0.f, 0.f);
    for (int c = clo; c <= chi; c++) {
        int st = JSTART(c);
        int slot = 2 * c + (((st >> 7) == Q) ? 0 : 1);
        l += g_lpart[slot * 2 * BM + lr] + g_lpart[slot * 2 * BM + BM + lr];
        float4 v = ((const float4*)(g_opart + ((size_t)slot << 15)
                                    + (size_t)lr * DDIM))[c4];
        acc.x += v.x; acc.y += v.y; acc.z += v.z; acc.w += v.w;
    }
    float inv = 1.0f / l;
    ((float4*)out)[idx] = make_float4(acc.x * inv, acc.y * inv,
                                      acc.z * inv, acc.w * inv);
}

extern "C" void kernel_launch(void* const* d_in, const int* in_sizes, int n_in,
                              void* d_out, int out_size) {
    const float* q  = (const float*)d_in[0];
    const float* cp = (const float*)d_in[1];
    float* out      = (float*)d_out;

    cudaFuncSetAttribute(hyp_fa_kernel,
                         cudaFuncAttributeMaxDynamicSharedMemorySize, SMEM_TOTAL);

    prep_kernel<<<NROWS / 8, 256>>>(q, cp);
    hyp_fa_kernel<<<NCTA, NTHREADS, SMEM_TOTAL>>>(cp);
    combine_kernel<<<2048, 256>>>(out);
}